// round 1
// baseline (speedup 1.0000x reference)
#include <cuda_runtime.h>

// GRU_90821378441798 — fused minGRU, linear-space scan, f32x2 packed FMA GEMM.
// B=4, N=64, L=1024, F=15, C=128, n_layers=2.
//
// Inputs (metadata order): xs(3840) x(262144) W1(2048) b1(128) W_gru(65536)
//                          W_out(128) b_out(1) [inputs train stage ignored]
// Output: float32 (B,N,L) = 262144.

#define LOG2E 1.4426950408889634f

// scratch (static device globals; no allocations)
__device__ float  d_Base[4 * 64 * 128];                 // xs@W1[1:,:]+b1, per (b,n,c)
__device__ float2 d_Wpack[2 * 128 * 128 + 1024];        // (Wg[k][c], Wg[k][c+128]) + pad for prefetch overread

static __device__ __forceinline__ unsigned long long pack2(float lo, float hi) {
    unsigned long long r;
    asm("mov.b64 %0, {%1, %2};" : "=l"(r) : "f"(lo), "f"(hi));
    return r;
}
static __device__ __forceinline__ void unpack2(unsigned long long v, float& lo, float& hi) {
    asm("mov.b64 {%0, %1}, %2;" : "=f"(lo), "=f"(hi) : "l"(v));
}
// d = a*b + d, packed 2xfp32 (sm_100+)
static __device__ __forceinline__ void ffma2(unsigned long long& d, unsigned long long a, unsigned long long b) {
    asm("fma.rn.f32x2 %0, %1, %2, %0;" : "+l"(d) : "l"(a), "l"(b));
}
static __device__ __forceinline__ float ex2f(float x) {
    float r; asm("ex2.approx.f32 %0, %1;" : "=f"(r) : "f"(x)); return r;
}
static __device__ __forceinline__ float rcpf(float x) {
    float r; asm("rcp.approx.f32 %0, %1;" : "=f"(r) : "f"(x)); return r;
}
static __device__ __forceinline__ float sigmoid_f(float x) {
    return rcpf(1.0f + ex2f(-LOG2E * x));
}

// base[b,n,c] = b1[c] + sum_f xs[b,n,f] * W1[1+f, c]
__global__ void base_kernel(const float* __restrict__ xs,
                            const float* __restrict__ W1,
                            const float* __restrict__ b1) {
    int row = blockIdx.x;      // b*64 + n, 0..255
    int c = threadIdx.x;       // 0..127
    float s = b1[c];
    const float* xr = xs + row * 15;
#pragma unroll
    for (int f = 0; f < 15; f++) s = fmaf(xr[f], W1[(f + 1) * 128 + c], s);
    d_Base[row * 128 + c] = s;
}

// Wpack[layer][k][c] = (Wg[layer][k][c], Wg[layer][k][c+128])
__global__ void pack_kernel(const float* __restrict__ Wg) {
    int layer = blockIdx.x >> 7;
    int k = blockIdx.x & 127;
    int c = threadIdx.x;
    const float* src = Wg + layer * 32768 + k * 256;
    d_Wpack[layer * 16384 + k * 128 + c] = make_float2(src[c], src[c + 128]);
}

__global__ void __launch_bounds__(128, 2)
gru_kernel(const float* __restrict__ x,
           const float* __restrict__ W1,
           const float* __restrict__ W_out,
           const float* __restrict__ b_out,
           float* __restrict__ out) {
    __shared__ float featsS[128][68];   // [channel][n], padded stride 68 (272B, 16B-aligned rows)
    __shared__ float xr[64];
    __shared__ float woutS[128];

    const int c = threadIdx.x;          // 0..127 = channel / output-column pair
    const int bid = blockIdx.x;         // b*1024 + l
    const int b = bid >> 10;
    const int l = bid & 1023;

    if (c < 64) xr[c] = x[(b * 64 + c) * 1024 + l];
    woutS[c] = W_out[c];
    const float bo = b_out[0];
    __syncthreads();

    // ---- layer-0 input: feats[c][n] = relu(x[b,n,l]*W1[0,c] + base[b,n,c]) ----
    {
        const float w1c = W1[c];                       // W1[0][c]
        const float* Bb = d_Base + b * 8192 + c;
#pragma unroll 8
        for (int n = 0; n < 64; n++) {
            float f = fmaf(xr[n], w1c, Bb[n * 128]);
            featsS[c][n] = fmaxf(f, 0.0f);
        }
    }
    __syncthreads();

    // ---- two GRU layers, fully fused ----
#pragma unroll 1
    for (int layer = 0; layer < 2; layer++) {
        // accumulators: packed pairs over n (n=2m, 2m+1); hidden col c, gate col c+128
        unsigned long long accH[32], accG[32];
#pragma unroll
        for (int m = 0; m < 32; m++) { accH[m] = 0ull; accG[m] = 0ull; }

        const float2* Wp = d_Wpack + layer * 16384 + c;
        float2 wb[4];
#pragma unroll
        for (int i = 0; i < 4; i++) wb[i] = Wp[i * 128];

        // GEMM: hg[n, {c, c+128}] = sum_k feats[n,k] * Wg[k, {c, c+128}]
#pragma unroll 1
        for (int k0 = 0; k0 < 128; k0 += 4) {
#pragma unroll
            for (int u = 0; u < 4; u++) {
                const int k = k0 + u;
                const float2 w = wb[u];
                wb[u] = Wp[(k + 4) * 128];             // prefetch (pad makes overread safe)
                const unsigned long long wh = pack2(w.x, w.x);
                const unsigned long long wg = pack2(w.y, w.y);
                const ulonglong2* fr = reinterpret_cast<const ulonglong2*>(&featsS[k][0]);
#pragma unroll
                for (int m = 0; m < 16; m++) {
                    ulonglong2 fv = fr[m];             // feats[k][4m..4m+3], warp-uniform broadcast
                    ffma2(accH[2 * m], fv.x, wh);
                    ffma2(accH[2 * m + 1], fv.y, wh);
                    ffma2(accG[2 * m], fv.x, wg);
                    ffma2(accG[2 * m + 1], fv.y, wg);
                }
            }
        }

        __syncthreads();   // all warps done reading featsS; safe to overwrite

        // ---- in-register minGRU scan over n (linear space, exactly equals Heinsen log-scan) ----
        // a = 1 - sigmoid(gate); v = sigmoid(gate) * g(hidden); h = a*h + v
        float h = 0.0f;
        float* dst = &featsS[c][0];
#pragma unroll
        for (int m = 0; m < 32; m++) {
            float h0, h1, g0, g1;
            unpack2(accH[m], h0, h1);
            unpack2(accG[m], g0, g1);
            {
                const float z = sigmoid_f(g0);
                const float sg = sigmoid_f(h0);
                const float g = (h0 >= 0.0f) ? (h0 + 0.5f) : sg;
                const float v = z * g;
                const float a = 1.0f - z;
                h = (m == 0) ? v : fmaf(a, h, v);
                dst[2 * m] = h;
            }
            {
                const float z = sigmoid_f(g1);
                const float sg = sigmoid_f(h1);
                const float g = (h1 >= 0.0f) ? (h1 + 0.5f) : sg;
                const float v = z * g;
                const float a = 1.0f - z;
                h = fmaf(a, h, v);
                dst[2 * m + 1] = h;
            }
        }
        __syncthreads();
    }

    // ---- output: out[b,n,l] = sum_c feats[c][n]*W_out[c] + b_out + x[b,n,l] ----
    if (c < 64) {
        const int n = c;
        float s0 = 0.f, s1 = 0.f, s2 = 0.f, s3 = 0.f;
#pragma unroll 8
        for (int q = 0; q < 128; q += 4) {
            s0 = fmaf(featsS[q + 0][n], woutS[q + 0], s0);
            s1 = fmaf(featsS[q + 1][n], woutS[q + 1], s1);
            s2 = fmaf(featsS[q + 2][n], woutS[q + 2], s2);
            s3 = fmaf(featsS[q + 3][n], woutS[q + 3], s3);
        }
        out[(b * 64 + n) * 1024 + l] = (s0 + s1) + (s2 + s3) + bo + xr[n];
    }
}

extern "C" void kernel_launch(void* const* d_in, const int* in_sizes, int n_in,
                              void* d_out, int out_size) {
    const float* xs = (const float*)d_in[0];
    const float* x  = (const float*)d_in[1];
    const float* W1 = (const float*)d_in[2];
    const float* b1 = (const float*)d_in[3];
    const float* Wg = (const float*)d_in[4];
    const float* Wo = (const float*)d_in[5];
    const float* bo = (const float*)d_in[6];
    float* out = (float*)d_out;

    base_kernel<<<256, 128>>>(xs, W1, b1);
    pack_kernel<<<256, 128>>>(Wg);
    gru_kernel<<<4096, 128>>>(x, W1, Wo, bo, out);
}

// round 2
// speedup vs baseline: 1.0014x; 1.0014x over previous
#include <cuda_runtime.h>

// GRU_90821378441798 — fused minGRU, linear-space scan, f32x2 packed FMA GEMM.
// B=4, N=64, L=1024, F=15, C=128, n_layers=2.
//
// Inputs (metadata order): xs(3840) x(262144) W1(2048) b1(128) W_gru(65536)
//                          W_out(128) b_out(1) [inputs train stage ignored]
// Output: float32 (B,N,L) = 262144.

#define LOG2E 1.4426950408889634f

// scratch (static device globals; no allocations)
__device__ float  d_Base[4 * 64 * 128];                 // xs@W1[1:,:]+b1, per (b,n,c)
__device__ float2 d_Wpack[2 * 128 * 128 + 1024];        // (Wg[k][c], Wg[k][c+128]) + pad for prefetch overread

static __device__ __forceinline__ unsigned long long pack2(float lo, float hi) {
    unsigned long long r;
    asm("mov.b64 %0, {%1, %2};" : "=l"(r) : "f"(lo), "f"(hi));
    return r;
}
static __device__ __forceinline__ void unpack2(unsigned long long v, float& lo, float& hi) {
    asm("mov.b64 {%0, %1}, %2;" : "=f"(lo), "=f"(hi) : "l"(v));
}
// d = a*b + d, packed 2xfp32 (sm_100+)
static __device__ __forceinline__ void ffma2(unsigned long long& d, unsigned long long a, unsigned long long b) {
    asm("fma.rn.f32x2 %0, %1, %2, %0;" : "+l"(d) : "l"(a), "l"(b));
}
static __device__ __forceinline__ float ex2f(float x) {
    float r; asm("ex2.approx.f32 %0, %1;" : "=f"(r) : "f"(x)); return r;
}
static __device__ __forceinline__ float rcpf(float x) {
    float r; asm("rcp.approx.f32 %0, %1;" : "=f"(r) : "f"(x)); return r;
}
static __device__ __forceinline__ float sigmoid_f(float x) {
    return rcpf(1.0f + ex2f(-LOG2E * x));
}

// base[b,n,c] = b1[c] + sum_f xs[b,n,f] * W1[1+f, c]
__global__ void base_kernel(const float* __restrict__ xs,
                            const float* __restrict__ W1,
                            const float* __restrict__ b1) {
    int row = blockIdx.x;      // b*64 + n, 0..255
    int c = threadIdx.x;       // 0..127
    float s = b1[c];
    const float* xr = xs + row * 15;
#pragma unroll
    for (int f = 0; f < 15; f++) s = fmaf(xr[f], W1[(f + 1) * 128 + c], s);
    d_Base[row * 128 + c] = s;
}

// Wpack[layer][k][c] = (Wg[layer][k][c], Wg[layer][k][c+128])
__global__ void pack_kernel(const float* __restrict__ Wg) {
    int layer = blockIdx.x >> 7;
    int k = blockIdx.x & 127;
    int c = threadIdx.x;
    const float* src = Wg + layer * 32768 + k * 256;
    d_Wpack[layer * 16384 + k * 128 + c] = make_float2(src[c], src[c + 128]);
}

__global__ void __launch_bounds__(128, 2)
gru_kernel(const float* __restrict__ x,
           const float* __restrict__ W1,
           const float* __restrict__ W_out,
           const float* __restrict__ b_out,
           float* __restrict__ out) {
    __shared__ float featsS[128][68];   // [channel][n], padded stride 68 (272B, 16B-aligned rows)
    __shared__ float xr[64];
    __shared__ float woutS[128];

    const int c = threadIdx.x;          // 0..127 = channel / output-column pair
    const int bid = blockIdx.x;         // b*1024 + l
    const int b = bid >> 10;
    const int l = bid & 1023;

    if (c < 64) xr[c] = x[(b * 64 + c) * 1024 + l];
    woutS[c] = W_out[c];
    const float bo = b_out[0];
    __syncthreads();

    // ---- layer-0 input: feats[c][n] = relu(x[b,n,l]*W1[0,c] + base[b,n,c]) ----
    {
        const float w1c = W1[c];                       // W1[0][c]
        const float* Bb = d_Base + b * 8192 + c;
#pragma unroll 8
        for (int n = 0; n < 64; n++) {
            float f = fmaf(xr[n], w1c, Bb[n * 128]);
            featsS[c][n] = fmaxf(f, 0.0f);
        }
    }
    __syncthreads();

    // ---- two GRU layers, fully fused ----
#pragma unroll 1
    for (int layer = 0; layer < 2; layer++) {
        // accumulators: packed pairs over n (n=2m, 2m+1); hidden col c, gate col c+128
        unsigned long long accH[32], accG[32];
#pragma unroll
        for (int m = 0; m < 32; m++) { accH[m] = 0ull; accG[m] = 0ull; }

        const float2* Wp = d_Wpack + layer * 16384 + c;
        float2 wb[4];
#pragma unroll
        for (int i = 0; i < 4; i++) wb[i] = Wp[i * 128];

        // GEMM: hg[n, {c, c+128}] = sum_k feats[n,k] * Wg[k, {c, c+128}]
#pragma unroll 1
        for (int k0 = 0; k0 < 128; k0 += 4) {
#pragma unroll
            for (int u = 0; u < 4; u++) {
                const int k = k0 + u;
                const float2 w = wb[u];
                wb[u] = Wp[(k + 4) * 128];             // prefetch (pad makes overread safe)
                const unsigned long long wh = pack2(w.x, w.x);
                const unsigned long long wg = pack2(w.y, w.y);
                const ulonglong2* fr = reinterpret_cast<const ulonglong2*>(&featsS[k][0]);
#pragma unroll
                for (int m = 0; m < 16; m++) {
                    ulonglong2 fv = fr[m];             // feats[k][4m..4m+3], warp-uniform broadcast
                    ffma2(accH[2 * m], fv.x, wh);
                    ffma2(accH[2 * m + 1], fv.y, wh);
                    ffma2(accG[2 * m], fv.x, wg);
                    ffma2(accG[2 * m + 1], fv.y, wg);
                }
            }
        }

        __syncthreads();   // all warps done reading featsS; safe to overwrite

        // ---- in-register minGRU scan over n (linear space, exactly equals Heinsen log-scan) ----
        // a = 1 - sigmoid(gate); v = sigmoid(gate) * g(hidden); h = a*h + v
        float h = 0.0f;
        float* dst = &featsS[c][0];
#pragma unroll
        for (int m = 0; m < 32; m++) {
            float h0, h1, g0, g1;
            unpack2(accH[m], h0, h1);
            unpack2(accG[m], g0, g1);
            {
                const float z = sigmoid_f(g0);
                const float sg = sigmoid_f(h0);
                const float g = (h0 >= 0.0f) ? (h0 + 0.5f) : sg;
                const float v = z * g;
                const float a = 1.0f - z;
                h = (m == 0) ? v : fmaf(a, h, v);
                dst[2 * m] = h;
            }
            {
                const float z = sigmoid_f(g1);
                const float sg = sigmoid_f(h1);
                const float g = (h1 >= 0.0f) ? (h1 + 0.5f) : sg;
                const float v = z * g;
                const float a = 1.0f - z;
                h = fmaf(a, h, v);
                dst[2 * m + 1] = h;
            }
        }
        __syncthreads();
    }

    // ---- output: out[b,n,l] = sum_c feats[c][n]*W_out[c] + b_out + x[b,n,l] ----
    if (c < 64) {
        const int n = c;
        float s0 = 0.f, s1 = 0.f, s2 = 0.f, s3 = 0.f;
#pragma unroll 8
        for (int q = 0; q < 128; q += 4) {
            s0 = fmaf(featsS[q + 0][n], woutS[q + 0], s0);
            s1 = fmaf(featsS[q + 1][n], woutS[q + 1], s1);
            s2 = fmaf(featsS[q + 2][n], woutS[q + 2], s2);
            s3 = fmaf(featsS[q + 3][n], woutS[q + 3], s3);
        }
        out[(b * 64 + n) * 1024 + l] = (s0 + s1) + (s2 + s3) + bo + xr[n];
    }
}

extern "C" void kernel_launch(void* const* d_in, const int* in_sizes, int n_in,
                              void* d_out, int out_size) {
    const float* xs = (const float*)d_in[0];
    const float* x  = (const float*)d_in[1];
    const float* W1 = (const float*)d_in[2];
    const float* b1 = (const float*)d_in[3];
    const float* Wg = (const float*)d_in[4];
    const float* Wo = (const float*)d_in[5];
    const float* bo = (const float*)d_in[6];
    float* out = (float*)d_out;

    base_kernel<<<256, 128>>>(xs, W1, b1);
    pack_kernel<<<256, 128>>>(Wg);
    gru_kernel<<<4096, 128>>>(x, W1, Wo, bo, out);
}

// round 4
// speedup vs baseline: 1.4509x; 1.4488x over previous
#include <cuda_runtime.h>
#include <cuda_bf16.h>
#include <cstdint>

// GRU_90821378441798 — mma.sync (HMMA) bf16-split GEMM + in-register minGRU scan.
// B=4, N=64, L=1024, C=128, 2 layers. CTA = (b,l), grid 4096, 128 threads.
// No sm_100a features: mma.sync / ldmatrix only (sm_80+ PTX).

#define LOG2E 1.4426950408889634f

// smem layout (bytes)
#define FEATS_HI 0
#define FEATS_LO 16384
#define HG_OFF   32768          // 64 rows x 1056B (264 floats, 256 used)
#define HG_STRIDE 1056
#define XR_OFF   100352         // 64 floats
#define W1S_OFF  100608         // 128 floats
#define WOUT_OFF 101120         // 128 floats
#define SMEM_TOTAL 101632

__device__ float d_Base[4 * 64 * 128];                    // xs@W1[1:,:]+b1
__device__ __align__(16) uint4 d_Wfrag[2 * 8 * 32 * 32];  // [layer][kt][nt][lane] = {bhi0,bhi1,blo0,blo1}

static __device__ __forceinline__ uint32_t smem_u32(const void* p) {
    uint32_t a;
    asm("{ .reg .u64 t; cvta.to.shared.u64 t, %1; cvt.u32.u64 %0, t; }" : "=r"(a) : "l"(p));
    return a;
}
static __device__ __forceinline__ float ex2f(float x) { float r; asm("ex2.approx.f32 %0, %1;" : "=f"(r) : "f"(x)); return r; }
static __device__ __forceinline__ float rcpf(float x) { float r; asm("rcp.approx.f32 %0, %1;" : "=f"(r) : "f"(x)); return r; }
static __device__ __forceinline__ float sigmoid_f(float x) { return rcpf(1.0f + ex2f(-LOG2E * x)); }

static __device__ __forceinline__ void ldsm4(uint32_t* r, uint32_t addr) {
    asm volatile("ldmatrix.sync.aligned.m8n8.x4.shared.b16 {%0,%1,%2,%3}, [%4];"
                 : "=r"(r[0]), "=r"(r[1]), "=r"(r[2]), "=r"(r[3]) : "r"(addr));
}
static __device__ __forceinline__ void mma16816(float* c, const uint32_t* a, uint32_t b0, uint32_t b1) {
    asm volatile("mma.sync.aligned.m16n8k16.row.col.f32.bf16.bf16.f32 "
                 "{%0,%1,%2,%3},{%4,%5,%6,%7},{%8,%9},{%0,%1,%2,%3};"
                 : "+f"(c[0]), "+f"(c[1]), "+f"(c[2]), "+f"(c[3])
                 : "r"(a[0]), "r"(a[1]), "r"(a[2]), "r"(a[3]), "r"(b0), "r"(b1));
}
static __device__ __forceinline__ uint32_t bfpack(float a, float b) {  // low=a, high=b
    return ((uint32_t)__bfloat16_as_ushort(__float2bfloat16(b)) << 16)
         | (uint32_t)__bfloat16_as_ushort(__float2bfloat16(a));
}
static __device__ __forceinline__ float bfres(float w) {   // residual after bf16 truncation
    return w - __bfloat162float(__float2bfloat16(w));
}

// ---------- prep kernels ----------
__global__ void base_kernel(const float* __restrict__ xs,
                            const float* __restrict__ W1,
                            const float* __restrict__ b1) {
    int row = blockIdx.x, c = threadIdx.x;
    float s = b1[c];
    const float* xr = xs + row * 15;
#pragma unroll
    for (int f = 0; f < 15; f++) s = fmaf(xr[f], W1[(f + 1) * 128 + c], s);
    d_Base[row * 128 + c] = s;
}

// Fragment-ordered weight pack for mma.sync B operand (col-major k16 x n8).
// b0: k = kt*16 + 2*(lane&3)+{0,1}, n = nt*8 + (lane>>2); b1: k += 8.
__global__ void pack_w_kernel(const float* __restrict__ Wg) {
    int idx = blockIdx.x * 256 + threadIdx.x;        // 16384
    int lane = idx & 31;
    int nt = (idx >> 5) & 31;
    int kt = (idx >> 10) & 7;
    int layer = idx >> 13;
    int n = nt * 8 + (lane >> 2);
    int k0 = kt * 16 + 2 * (lane & 3);
    const float* Wl = Wg + layer * 32768;
    float w00 = Wl[k0 * 256 + n];
    float w01 = Wl[(k0 + 1) * 256 + n];
    float w10 = Wl[(k0 + 8) * 256 + n];
    float w11 = Wl[(k0 + 9) * 256 + n];
    uint4 v;
    v.x = bfpack(w00, w01);                 // bhi0
    v.y = bfpack(w10, w11);                 // bhi1
    v.z = bfpack(bfres(w00), bfres(w01));   // blo0
    v.w = bfpack(bfres(w10), bfres(w11));   // blo1
    d_Wfrag[idx] = v;
}

// ---------- main kernel ----------
__global__ void __launch_bounds__(128, 2)
gru_mma_kernel(const float* __restrict__ x,
               const float* __restrict__ W1,
               const float* __restrict__ W_out,
               const float* __restrict__ b_out,
               float* __restrict__ out) {
    extern __shared__ __align__(128) char sm[];
    const uint32_t sbase = smem_u32(sm);

    const int tid = threadIdx.x;
    const int w = tid >> 5;
    const int t = tid & 31;
    const int b = blockIdx.x >> 10;
    const int l = blockIdx.x & 1023;

    float* xr = (float*)(sm + XR_OFF);
    float* w1s = (float*)(sm + W1S_OFF);
    float* wouts = (float*)(sm + WOUT_OFF);

    if (tid < 64) xr[tid] = x[(b * 64 + tid) * 1024 + l];
    w1s[tid] = W1[tid];
    wouts[tid] = W_out[tid];
    __syncthreads();

    // ---- layer-0 feats: relu(x*W1[0,c] + base) -> swizzled bf16 hi/lo A tiles ----
    // feats row n (0..63), 256B/row; 16B unit u stored at (u ^ (n&7)).
    {
        const float4* base4 = (const float4*)d_Base;
        const float4* w14 = (const float4*)w1s;
#pragma unroll
        for (int it = 0; it < 16; it++) {
            int i = tid + 128 * it;        // 2048 items
            int r = i >> 5, j = i & 31;    // row n = r, channels 4j..4j+3
            float4 bs = base4[(b * 64 + r) * 32 + j];
            float4 wv = w14[j];
            float xv = xr[r];
            float v0 = fmaxf(fmaf(xv, wv.x, bs.x), 0.0f);
            float v1 = fmaxf(fmaf(xv, wv.y, bs.y), 0.0f);
            float v2 = fmaxf(fmaf(xv, wv.z, bs.z), 0.0f);
            float v3 = fmaxf(fmaf(xv, wv.w, bs.w), 0.0f);
            uint32_t h01 = bfpack(v0, v1), h23 = bfpack(v2, v3);
            uint32_t l01 = bfpack(bfres(v0), bfres(v1)), l23 = bfpack(bfres(v2), bfres(v3));
            int off = r * 256 + ((((j >> 1) ^ (r & 7))) << 4) + 8 * (j & 1);
            *(uint2*)(sm + FEATS_HI + off) = make_uint2(h01, h23);
            *(uint2*)(sm + FEATS_LO + off) = make_uint2(l01, l23);
        }
    }
    __syncthreads();

#pragma unroll 1
    for (int layer = 0; layer < 2; layer++) {
        // ---- GEMM: warp w owns output cols [w*64, w*64+64) ----
        float acc[128];
#pragma unroll
        for (int i = 0; i < 128; i++) acc[i] = 0.0f;

        const uint4* wl = d_Wfrag + layer * 8192 + w * 256 + t;

#pragma unroll 1
        for (int kt = 0; kt < 8; kt++) {
            uint32_t Ah[16], Al[16];
#pragma unroll
            for (int mt = 0; mt < 4; mt++) {
                int row = 16 * mt + (t & 7) + ((t >> 3) & 1) * 8;
                uint32_t unit = (uint32_t)(2 * kt + (t >> 4));
                uint32_t off = (uint32_t)(row * 256) + ((unit ^ (uint32_t)(row & 7)) << 4);
                ldsm4(Ah + 4 * mt, sbase + FEATS_HI + off);
                ldsm4(Al + 4 * mt, sbase + FEATS_LO + off);
            }
#pragma unroll
            for (int nt = 0; nt < 8; nt++) {
                uint4 bw = wl[kt * 1024 + nt * 32];
#pragma unroll
                for (int mt = 0; mt < 4; mt++) {
                    float* c = acc + (nt * 4 + mt) * 4;
                    mma16816(c, Ah + 4 * mt, bw.x, bw.y);   // hi*hi
                    mma16816(c, Ah + 4 * mt, bw.z, bw.w);   // hi*lo
                    mma16816(c, Al + 4 * mt, bw.x, bw.y);   // lo*hi
                }
            }
        }

        // ---- store hg fragments to smem [n][256c] fp32 (stride 264 words) ----
#pragma unroll
        for (int nt = 0; nt < 8; nt++) {
            int col = (w * 8 + nt) * 8 + 2 * (t & 3);
#pragma unroll
            for (int mt = 0; mt < 4; mt++) {
                int r0 = 16 * mt + (t >> 2);
                const float* c = acc + (nt * 4 + mt) * 4;
                *(float2*)(sm + HG_OFF + r0 * HG_STRIDE + col * 4) = make_float2(c[0], c[1]);
                *(float2*)(sm + HG_OFF + (r0 + 8) * HG_STRIDE + col * 4) = make_float2(c[2], c[3]);
            }
        }
        __syncthreads();

        // ---- minGRU scan over n, channel c = tid ----
        {
            const int c = tid;
            float h = 0.0f;
#pragma unroll
            for (int n = 0; n < 64; n++) {
                float hid = *(const float*)(sm + HG_OFF + n * HG_STRIDE + c * 4);
                float gat = *(const float*)(sm + HG_OFF + n * HG_STRIDE + (c + 128) * 4);
                float z = sigmoid_f(gat);
                float gg = (hid >= 0.0f) ? (hid + 0.5f) : sigmoid_f(hid);
                float v = z * gg;
                h = (n == 0) ? v : fmaf(1.0f - z, h, v);
                if (layer == 0) {
                    // write next-layer feats (hi/lo bf16, swizzled)
                    int off = n * 256 + ((((c >> 3) ^ (n & 7))) << 4) + ((2 * c) & 14);
                    *(__nv_bfloat16*)(sm + FEATS_HI + off) = __float2bfloat16(h);
                    *(__nv_bfloat16*)(sm + FEATS_LO + off) = __float2bfloat16(bfres(h));
                } else {
                    // in-place: cell (n,c<128) is only ever touched by this thread
                    *(float*)(sm + HG_OFF + n * HG_STRIDE + c * 4) = h;
                }
            }
        }
        __syncthreads();
    }

    // ---- output: out[b,n,l] = sum_c h[n][c]*Wout[c] + b_out + x ----
    if (tid < 64) {
        const int n = tid;
        const float4* row4 = (const float4*)(sm + HG_OFF + n * HG_STRIDE);
        const float4* wo4 = (const float4*)wouts;
        float s0 = 0.f, s1 = 0.f, s2 = 0.f, s3 = 0.f;
#pragma unroll
        for (int q = 0; q < 32; q++) {
            float4 hv = row4[q];
            float4 wv = wo4[q];
            s0 = fmaf(hv.x, wv.x, s0);
            s1 = fmaf(hv.y, wv.y, s1);
            s2 = fmaf(hv.z, wv.z, s2);
            s3 = fmaf(hv.w, wv.w, s3);
        }
        out[(b * 64 + n) * 1024 + l] = (s0 + s1) + (s2 + s3) + b_out[0] + xr[n];
    }
}

extern "C" void kernel_launch(void* const* d_in, const int* in_sizes, int n_in,
                              void* d_out, int out_size) {
    const float* xs = (const float*)d_in[0];
    const float* x  = (const float*)d_in[1];
    const float* W1 = (const float*)d_in[2];
    const float* b1 = (const float*)d_in[3];
    const float* Wg = (const float*)d_in[4];
    const float* Wo = (const float*)d_in[5];
    const float* bo = (const float*)d_in[6];
    float* out = (float*)d_out;

    cudaFuncSetAttribute(gru_mma_kernel, cudaFuncAttributeMaxDynamicSharedMemorySize, SMEM_TOTAL);
    base_kernel<<<256, 128>>>(xs, W1, b1);
    pack_w_kernel<<<64, 256>>>(Wg);
    gru_mma_kernel<<<4096, 128, SMEM_TOTAL>>>(x, W1, Wo, bo, out);
}

// round 5
// speedup vs baseline: 1.7960x; 1.2379x over previous
#include <cuda_runtime.h>
#include <cuda_bf16.h>
#include <cstdint>

// GRU_90821378441798 — mma.sync (HMMA) 2-product bf16 split GEMM + in-register minGRU scan.
// B=4, N=64, L=1024, C=128, 2 layers. CTA = (b,l), grid 4096, 128 threads.
// hg = A_hi * (B_hi + B_lo): A = feats (bf16), B = weights (hi+lo bf16 split, err 2^-18).

#define LOG2E 1.4426950408889634f

// smem layout (bytes)
#define FEATS_HI 0              // 64 rows x 256B swizzled bf16
#define HG_OFF   16384          // 64 rows x 1056B (264 floats, 256 used)
#define HG_STRIDE 1056
#define XR_OFF   83968          // 64 floats
#define W1S_OFF  84224          // 128 floats
#define WOUT_OFF 84736          // 128 floats
#define SMEM_TOTAL 85248

__device__ float d_Base[4 * 64 * 128];                    // xs@W1[1:,:]+b1
__device__ __align__(16) uint4 d_Wfrag[2 * 8 * 32 * 32];  // [layer][kt][nt][lane] = {bhi0,bhi1,blo0,blo1}

static __device__ __forceinline__ uint32_t smem_u32(const void* p) {
    uint32_t a;
    asm("{ .reg .u64 t; cvta.to.shared.u64 t, %1; cvt.u32.u64 %0, t; }" : "=r"(a) : "l"(p));
    return a;
}
static __device__ __forceinline__ float ex2f(float x) { float r; asm("ex2.approx.f32 %0, %1;" : "=f"(r) : "f"(x)); return r; }
static __device__ __forceinline__ float rcpf(float x) { float r; asm("rcp.approx.f32 %0, %1;" : "=f"(r) : "f"(x)); return r; }
static __device__ __forceinline__ float sigmoid_f(float x) { return rcpf(1.0f + ex2f(-LOG2E * x)); }

static __device__ __forceinline__ void ldsm4(uint32_t* r, uint32_t addr) {
    asm volatile("ldmatrix.sync.aligned.m8n8.x4.shared.b16 {%0,%1,%2,%3}, [%4];"
                 : "=r"(r[0]), "=r"(r[1]), "=r"(r[2]), "=r"(r[3]) : "r"(addr));
}
static __device__ __forceinline__ void mma16816(float* c, const uint32_t* a, uint32_t b0, uint32_t b1) {
    asm volatile("mma.sync.aligned.m16n8k16.row.col.f32.bf16.bf16.f32 "
                 "{%0,%1,%2,%3},{%4,%5,%6,%7},{%8,%9},{%0,%1,%2,%3};"
                 : "+f"(c[0]), "+f"(c[1]), "+f"(c[2]), "+f"(c[3])
                 : "r"(a[0]), "r"(a[1]), "r"(a[2]), "r"(a[3]), "r"(b0), "r"(b1));
}
static __device__ __forceinline__ uint32_t bfpack(float a, float b) {  // low=a, high=b
    return ((uint32_t)__bfloat16_as_ushort(__float2bfloat16(b)) << 16)
         | (uint32_t)__bfloat16_as_ushort(__float2bfloat16(a));
}
static __device__ __forceinline__ float bfres(float w) {   // residual after bf16 truncation
    return w - __bfloat162float(__float2bfloat16(w));
}

// ---------- merged prep kernel ----------
// blocks [0,64): weight fragment pack (256 thr). blocks [64,192): base rows (2 rows/block).
__global__ void prep_kernel(const float* __restrict__ xs,
                            const float* __restrict__ W1,
                            const float* __restrict__ b1,
                            const float* __restrict__ Wg) {
    if (blockIdx.x < 64) {
        int idx = blockIdx.x * 256 + threadIdx.x;        // 16384
        int lane = idx & 31;
        int nt = (idx >> 5) & 31;
        int kt = (idx >> 10) & 7;
        int layer = idx >> 13;
        int n = nt * 8 + (lane >> 2);
        int k0 = kt * 16 + 2 * (lane & 3);
        const float* Wl = Wg + layer * 32768;
        float w00 = Wl[k0 * 256 + n];
        float w01 = Wl[(k0 + 1) * 256 + n];
        float w10 = Wl[(k0 + 8) * 256 + n];
        float w11 = Wl[(k0 + 9) * 256 + n];
        uint4 v;
        v.x = bfpack(w00, w01);                 // bhi0
        v.y = bfpack(w10, w11);                 // bhi1
        v.z = bfpack(bfres(w00), bfres(w01));   // blo0
        v.w = bfpack(bfres(w10), bfres(w11));   // blo1
        d_Wfrag[idx] = v;
    } else {
        int row = (blockIdx.x - 64) * 2 + (threadIdx.x >> 7);   // 0..255
        int c = threadIdx.x & 127;
        float s = b1[c];
        const float* xr = xs + row * 15;
#pragma unroll
        for (int f = 0; f < 15; f++) s = fmaf(xr[f], W1[(f + 1) * 128 + c], s);
        d_Base[row * 128 + c] = s;
    }
}

// ---------- main kernel ----------
__global__ void __launch_bounds__(128, 2)
gru_mma_kernel(const float* __restrict__ x,
               const float* __restrict__ W1,
               const float* __restrict__ W_out,
               const float* __restrict__ b_out,
               float* __restrict__ out) {
    extern __shared__ __align__(128) char sm[];
    const uint32_t sbase = smem_u32(sm);

    const int tid = threadIdx.x;
    const int w = tid >> 5;
    const int t = tid & 31;
    const int b = blockIdx.x >> 10;
    const int l = blockIdx.x & 1023;

    float* xr = (float*)(sm + XR_OFF);
    float* w1s = (float*)(sm + W1S_OFF);
    float* wouts = (float*)(sm + WOUT_OFF);

    if (tid < 64) xr[tid] = x[(b * 64 + tid) * 1024 + l];
    w1s[tid] = W1[tid];
    wouts[tid] = W_out[tid];
    __syncthreads();

    // ---- layer-0 feats: relu(x*W1[0,c] + base) -> swizzled bf16 A tile ----
    // row n: 256B; 16B unit u stored at (u ^ (n&7)).
    {
        const float4* base4 = (const float4*)d_Base;
        const float4* w14 = (const float4*)w1s;
#pragma unroll
        for (int it = 0; it < 16; it++) {
            int i = tid + 128 * it;        // 2048 items
            int r = i >> 5, j = i & 31;    // row n = r, channels 4j..4j+3
            float4 bs = base4[(b * 64 + r) * 32 + j];
            float4 wv = w14[j];
            float xv = xr[r];
            float v0 = fmaxf(fmaf(xv, wv.x, bs.x), 0.0f);
            float v1 = fmaxf(fmaf(xv, wv.y, bs.y), 0.0f);
            float v2 = fmaxf(fmaf(xv, wv.z, bs.z), 0.0f);
            float v3 = fmaxf(fmaf(xv, wv.w, bs.w), 0.0f);
            int off = r * 256 + ((((j >> 1) ^ (r & 7))) << 4) + 8 * (j & 1);
            *(uint2*)(sm + FEATS_HI + off) = make_uint2(bfpack(v0, v1), bfpack(v2, v3));
        }
    }
    __syncthreads();

#pragma unroll 1
    for (int layer = 0; layer < 2; layer++) {
        // ---- GEMM: warp w owns output cols [w*64, w*64+64) ----
        float acc[128];
#pragma unroll
        for (int i = 0; i < 128; i++) acc[i] = 0.0f;

        const uint4* wl = d_Wfrag + layer * 8192 + w * 256 + t;
        // flattened (kt,nt) index -> element offset
#define WADDR(idx) wl[(((idx) >> 3) << 10) + (((idx) & 7) << 5)]
        uint4 p0 = WADDR(0);
        uint4 p1 = WADDR(1);

#pragma unroll 1
        for (int kt = 0; kt < 8; kt++) {
            uint32_t Ah[16];
#pragma unroll
            for (int mt = 0; mt < 4; mt++) {
                int row = 16 * mt + (t & 7) + ((t >> 3) & 1) * 8;
                uint32_t unit = (uint32_t)(2 * kt + (t >> 4));
                uint32_t off = (uint32_t)(row * 256) + ((unit ^ (uint32_t)(row & 7)) << 4);
                ldsm4(Ah + 4 * mt, sbase + FEATS_HI + off);
            }
#pragma unroll
            for (int nt = 0; nt < 8; nt++) {
                uint4 bw = p0;
                p0 = p1;
                int ni = kt * 8 + nt + 2;            // distance-2 prefetch
                if (ni > 63) ni = 63;
                p1 = WADDR(ni);
#pragma unroll
                for (int mt = 0; mt < 4; mt++) {
                    float* c = acc + (nt * 4 + mt) * 4;
                    mma16816(c, Ah + 4 * mt, bw.x, bw.y);   // A_hi * B_hi
                    mma16816(c, Ah + 4 * mt, bw.z, bw.w);   // A_hi * B_lo
                }
            }
        }
#undef WADDR

        // ---- store hg fragments to smem [n][256c] fp32 (stride 264 words) ----
#pragma unroll
        for (int nt = 0; nt < 8; nt++) {
            int col = (w * 8 + nt) * 8 + 2 * (t & 3);
#pragma unroll
            for (int mt = 0; mt < 4; mt++) {
                int r0 = 16 * mt + (t >> 2);
                const float* c = acc + (nt * 4 + mt) * 4;
                *(float2*)(sm + HG_OFF + r0 * HG_STRIDE + col * 4) = make_float2(c[0], c[1]);
                *(float2*)(sm + HG_OFF + (r0 + 8) * HG_STRIDE + col * 4) = make_float2(c[2], c[3]);
            }
        }
        __syncthreads();

        // ---- minGRU scan over n, channel c = tid ----
        {
            const int c = tid;
            float h = 0.0f;
#pragma unroll
            for (int n = 0; n < 64; n++) {
                float hid = *(const float*)(sm + HG_OFF + n * HG_STRIDE + c * 4);
                float gat = *(const float*)(sm + HG_OFF + n * HG_STRIDE + (c + 128) * 4);
                float z = sigmoid_f(gat);
                float gg = (hid >= 0.0f) ? (hid + 0.5f) : sigmoid_f(hid);
                float v = z * gg;
                h = (n == 0) ? v : fmaf(1.0f - z, h, v);
                if (layer == 0) {
                    int off = n * 256 + ((((c >> 3) ^ (n & 7))) << 4) + ((2 * c) & 14);
                    *(__nv_bfloat16*)(sm + FEATS_HI + off) = __float2bfloat16(h);
                } else {
                    *(float*)(sm + HG_OFF + n * HG_STRIDE + c * 4) = h;   // in-place, thread-private cell
                }
            }
        }
        __syncthreads();
    }

    // ---- output: out[b,n,l] = sum_c h[n][c]*Wout[c] + b_out + x ----
    if (tid < 64) {
        const int n = tid;
        const float4* row4 = (const float4*)(sm + HG_OFF + n * HG_STRIDE);
        const float4* wo4 = (const float4*)wouts;
        float s0 = 0.f, s1 = 0.f, s2 = 0.f, s3 = 0.f;
#pragma unroll
        for (int q = 0; q < 32; q++) {
            float4 hv = row4[q];
            float4 wv = wo4[q];
            s0 = fmaf(hv.x, wv.x, s0);
            s1 = fmaf(hv.y, wv.y, s1);
            s2 = fmaf(hv.z, wv.z, s2);
            s3 = fmaf(hv.w, wv.w, s3);
        }
        out[(b * 64 + n) * 1024 + l] = (s0 + s1) + (s2 + s3) + b_out[0] + xr[n];
    }
}

extern "C" void kernel_launch(void* const* d_in, const int* in_sizes, int n_in,
                              void* d_out, int out_size) {
    const float* xs = (const float*)d_in[0];
    const float* x  = (const float*)d_in[1];
    const float* W1 = (const float*)d_in[2];
    const float* b1 = (const float*)d_in[3];
    const float* Wg = (const float*)d_in[4];
    const float* Wo = (const float*)d_in[5];
    const float* bo = (const float*)d_in[6];
    float* out = (float*)d_out;

    cudaFuncSetAttribute(gru_mma_kernel, cudaFuncAttributeMaxDynamicSharedMemorySize, SMEM_TOTAL);
    prep_kernel<<<192, 256>>>(xs, W1, b1, Wg);
    gru_mma_kernel<<<4096, 128, SMEM_TOTAL>>>(x, W1, Wo, bo, out);
}

// round 6
// speedup vs baseline: 1.8789x; 1.0462x over previous
#include <cuda_runtime.h>
#include <cuda_bf16.h>
#include <cstdint>

// GRU_90821378441798 — mma.sync (HMMA) 2-product bf16 split GEMM + in-register minGRU scan.
// R6: accumulator-RAW-free mma ordering (products outer, 32-issue spacing) +
//     double-buffered weight fragments across kt.

#define LOG2E 1.4426950408889634f

#define FEATS_HI 0              // 64 rows x 256B swizzled bf16
#define HG_OFF   16384          // 64 rows x 1056B (264 floats, 256 used)
#define HG_STRIDE 1056
#define XR_OFF   83968
#define W1S_OFF  84224
#define WOUT_OFF 84736
#define SMEM_TOTAL 85248

__device__ float d_Base[4 * 64 * 128];                    // xs@W1[1:,:]+b1
__device__ __align__(16) uint4 d_Wfrag[2 * 8 * 32 * 32];  // [layer][kt][nt][lane] = {bhi0,bhi1,blo0,blo1}

static __device__ __forceinline__ uint32_t smem_u32(const void* p) {
    uint32_t a;
    asm("{ .reg .u64 t; cvta.to.shared.u64 t, %1; cvt.u32.u64 %0, t; }" : "=r"(a) : "l"(p));
    return a;
}
static __device__ __forceinline__ float ex2f(float x) { float r; asm("ex2.approx.f32 %0, %1;" : "=f"(r) : "f"(x)); return r; }
static __device__ __forceinline__ float rcpf(float x) { float r; asm("rcp.approx.f32 %0, %1;" : "=f"(r) : "f"(x)); return r; }
static __device__ __forceinline__ float sigmoid_f(float x) { return rcpf(1.0f + ex2f(-LOG2E * x)); }

static __device__ __forceinline__ void ldsm4(uint32_t* r, uint32_t addr) {
    asm volatile("ldmatrix.sync.aligned.m8n8.x4.shared.b16 {%0,%1,%2,%3}, [%4];"
                 : "=r"(r[0]), "=r"(r[1]), "=r"(r[2]), "=r"(r[3]) : "r"(addr));
}
static __device__ __forceinline__ void mma16816(float* c, const uint32_t* a, uint32_t b0, uint32_t b1) {
    asm volatile("mma.sync.aligned.m16n8k16.row.col.f32.bf16.bf16.f32 "
                 "{%0,%1,%2,%3},{%4,%5,%6,%7},{%8,%9},{%0,%1,%2,%3};"
                 : "+f"(c[0]), "+f"(c[1]), "+f"(c[2]), "+f"(c[3])
                 : "r"(a[0]), "r"(a[1]), "r"(a[2]), "r"(a[3]), "r"(b0), "r"(b1));
}
static __device__ __forceinline__ uint32_t bfpack(float a, float b) {
    return ((uint32_t)__bfloat16_as_ushort(__float2bfloat16(b)) << 16)
         | (uint32_t)__bfloat16_as_ushort(__float2bfloat16(a));
}
static __device__ __forceinline__ float bfres(float w) {
    return w - __bfloat162float(__float2bfloat16(w));
}

// ---------- merged prep kernel ----------
__global__ void prep_kernel(const float* __restrict__ xs,
                            const float* __restrict__ W1,
                            const float* __restrict__ b1,
                            const float* __restrict__ Wg) {
    if (blockIdx.x < 64) {
        int idx = blockIdx.x * 256 + threadIdx.x;        // 16384
        int lane = idx & 31;
        int nt = (idx >> 5) & 31;
        int kt = (idx >> 10) & 7;
        int layer = idx >> 13;
        int n = nt * 8 + (lane >> 2);
        int k0 = kt * 16 + 2 * (lane & 3);
        const float* Wl = Wg + layer * 32768;
        float w00 = Wl[k0 * 256 + n];
        float w01 = Wl[(k0 + 1) * 256 + n];
        float w10 = Wl[(k0 + 8) * 256 + n];
        float w11 = Wl[(k0 + 9) * 256 + n];
        uint4 v;
        v.x = bfpack(w00, w01);
        v.y = bfpack(w10, w11);
        v.z = bfpack(bfres(w00), bfres(w01));
        v.w = bfpack(bfres(w10), bfres(w11));
        d_Wfrag[idx] = v;
    } else {
        int row = (blockIdx.x - 64) * 2 + (threadIdx.x >> 7);
        int c = threadIdx.x & 127;
        float s = b1[c];
        const float* xr = xs + row * 15;
#pragma unroll
        for (int f = 0; f < 15; f++) s = fmaf(xr[f], W1[(f + 1) * 128 + c], s);
        d_Base[row * 128 + c] = s;
    }
}

// ---------- main kernel ----------
__global__ void __launch_bounds__(128, 2)
gru_mma_kernel(const float* __restrict__ x,
               const float* __restrict__ W1,
               const float* __restrict__ W_out,
               const float* __restrict__ b_out,
               float* __restrict__ out) {
    extern __shared__ __align__(128) char sm[];
    const uint32_t sbase = smem_u32(sm);

    const int tid = threadIdx.x;
    const int w = tid >> 5;
    const int t = tid & 31;
    const int b = blockIdx.x >> 10;
    const int l = blockIdx.x & 1023;

    float* xr = (float*)(sm + XR_OFF);
    float* w1s = (float*)(sm + W1S_OFF);
    float* wouts = (float*)(sm + WOUT_OFF);

    if (tid < 64) xr[tid] = x[(b * 64 + tid) * 1024 + l];
    w1s[tid] = W1[tid];
    wouts[tid] = W_out[tid];
    __syncthreads();

    // ---- layer-0 feats -> swizzled bf16 A tile ----
    {
        const float4* base4 = (const float4*)d_Base;
        const float4* w14 = (const float4*)w1s;
#pragma unroll
        for (int it = 0; it < 16; it++) {
            int i = tid + 128 * it;
            int r = i >> 5, j = i & 31;
            float4 bs = base4[(b * 64 + r) * 32 + j];
            float4 wv = w14[j];
            float xv = xr[r];
            float v0 = fmaxf(fmaf(xv, wv.x, bs.x), 0.0f);
            float v1 = fmaxf(fmaf(xv, wv.y, bs.y), 0.0f);
            float v2 = fmaxf(fmaf(xv, wv.z, bs.z), 0.0f);
            float v3 = fmaxf(fmaf(xv, wv.w, bs.w), 0.0f);
            int off = r * 256 + ((((j >> 1) ^ (r & 7))) << 4) + 8 * (j & 1);
            *(uint2*)(sm + FEATS_HI + off) = make_uint2(bfpack(v0, v1), bfpack(v2, v3));
        }
    }
    __syncthreads();

#pragma unroll 1
    for (int layer = 0; layer < 2; layer++) {
        float acc[128];
#pragma unroll
        for (int i = 0; i < 128; i++) acc[i] = 0.0f;

        const uint4* wl = d_Wfrag + layer * 8192 + w * 256 + t;

        uint4 bw[2][8];
#pragma unroll
        for (int nt = 0; nt < 8; nt++) bw[0][nt] = wl[nt * 32];   // kt=0 fragments

#pragma unroll
        for (int kt = 0; kt < 8; kt++) {
            const int cur = kt & 1, nxt = cur ^ 1;

            uint32_t Ah[16];
#pragma unroll
            for (int mt = 0; mt < 4; mt++) {
                int row = 16 * mt + (t & 7) + ((t >> 3) & 1) * 8;
                uint32_t unit = (uint32_t)(2 * kt + (t >> 4));
                uint32_t off = (uint32_t)(row * 256) + ((unit ^ (uint32_t)(row & 7)) << 4);
                ldsm4(Ah + 4 * mt, sbase + FEATS_HI + off);
            }

            if (kt < 7) {                       // prefetch next kt's weights under the mma block
#pragma unroll
                for (int nt = 0; nt < 8; nt++) bw[nxt][nt] = wl[(kt + 1) * 1024 + nt * 32];
            }

            // products outer: same-acc dependent mmas are 32 issues apart
#pragma unroll
            for (int nt = 0; nt < 8; nt++)
#pragma unroll
                for (int mt = 0; mt < 4; mt++)
                    mma16816(acc + (nt * 4 + mt) * 4, Ah + 4 * mt, bw[cur][nt].x, bw[cur][nt].y);
#pragma unroll
            for (int nt = 0; nt < 8; nt++)
#pragma unroll
                for (int mt = 0; mt < 4; mt++)
                    mma16816(acc + (nt * 4 + mt) * 4, Ah + 4 * mt, bw[cur][nt].z, bw[cur][nt].w);
        }

        // ---- store hg fragments to smem [n][256c] fp32 ----
#pragma unroll
        for (int nt = 0; nt < 8; nt++) {
            int col = (w * 8 + nt) * 8 + 2 * (t & 3);
#pragma unroll
            for (int mt = 0; mt < 4; mt++) {
                int r0 = 16 * mt + (t >> 2);
                const float* c = acc + (nt * 4 + mt) * 4;
                *(float2*)(sm + HG_OFF + r0 * HG_STRIDE + col * 4) = make_float2(c[0], c[1]);
                *(float2*)(sm + HG_OFF + (r0 + 8) * HG_STRIDE + col * 4) = make_float2(c[2], c[3]);
            }
        }
        __syncthreads();

        // ---- minGRU scan over n, channel c = tid ----
        {
            const int c = tid;
            float h = 0.0f;
#pragma unroll
            for (int n = 0; n < 64; n++) {
                float hid = *(const float*)(sm + HG_OFF + n * HG_STRIDE + c * 4);
                float gat = *(const float*)(sm + HG_OFF + n * HG_STRIDE + (c + 128) * 4);
                float z = sigmoid_f(gat);
                float gg = (hid >= 0.0f) ? (hid + 0.5f) : sigmoid_f(hid);
                float v = z * gg;
                h = (n == 0) ? v : fmaf(1.0f - z, h, v);
                if (layer == 0) {
                    int off = n * 256 + ((((c >> 3) ^ (n & 7))) << 4) + ((2 * c) & 14);
                    *(__nv_bfloat16*)(sm + FEATS_HI + off) = __float2bfloat16(h);
                } else {
                    *(float*)(sm + HG_OFF + n * HG_STRIDE + c * 4) = h;
                }
            }
        }
        __syncthreads();
    }

    // ---- output ----
    if (tid < 64) {
        const int n = tid;
        const float4* row4 = (const float4*)(sm + HG_OFF + n * HG_STRIDE);
        const float4* wo4 = (const float4*)wouts;
        float s0 = 0.f, s1 = 0.f, s2 = 0.f, s3 = 0.f;
#pragma unroll
        for (int q = 0; q < 32; q++) {
            float4 hv = row4[q];
            float4 wv = wo4[q];
            s0 = fmaf(hv.x, wv.x, s0);
            s1 = fmaf(hv.y, wv.y, s1);
            s2 = fmaf(hv.z, wv.z, s2);
            s3 = fmaf(hv.w, wv.w, s3);
        }
        out[(b * 64 + n) * 1024 + l] = (s0 + s1) + (s2 + s3) + b_out[0] + xr[n];
    }
}

extern "C" void kernel_launch(void* const* d_in, const int* in_sizes, int n_in,
                              void* d_out, int out_size) {
    const float* xs = (const float*)d_in[0];
    const float* x  = (const float*)d_in[1];
    const float* W1 = (const float*)d_in[2];
    const float* b1 = (const float*)d_in[3];
    const float* Wg = (const float*)d_in[4];
    const float* Wo = (const float*)d_in[5];
    const float* bo = (const float*)d_in[6];
    float* out = (float*)d_out;

    cudaFuncSetAttribute(gru_mma_kernel, cudaFuncAttributeMaxDynamicSharedMemorySize, SMEM_TOTAL);
    prep_kernel<<<192, 256>>>(xs, W1, b1, Wg);
    gru_mma_kernel<<<4096, 128, SMEM_TOTAL>>>(x, W1, Wo, bo, out);
}

// round 7
// speedup vs baseline: 2.8040x; 1.4924x over previous
#include <cuda_runtime.h>
#include <cuda_bf16.h>
#include <cstdint>

// GRU_90821378441798 — HMMA 2-product bf16 split GEMM + in-register minGRU scan.
// R7: two 32-col passes per warp (acc[64], no spills), tanh-based sigmoid (1 MUFU),
//     conflict-free hg stride (260 words).

#define FEATS_HI 0              // 64 rows x 256B swizzled bf16
#define HG_OFF   16384          // 64 rows x 1040B (260 floats, 256 used)
#define HG_STRIDE 1040
#define XR_OFF   82944
#define W1S_OFF  83200
#define WOUT_OFF 83712
#define SMEM_TOTAL 84224

__device__ float d_Base[4 * 64 * 128];                    // xs@W1[1:,:]+b1
__device__ __align__(16) uint4 d_Wfrag[2 * 8 * 32 * 32];  // [layer][kt][nt][lane] = {bhi0,bhi1,blo0,blo1}

static __device__ __forceinline__ uint32_t smem_u32(const void* p) {
    uint32_t a;
    asm("{ .reg .u64 t; cvta.to.shared.u64 t, %1; cvt.u32.u64 %0, t; }" : "=r"(a) : "l"(p));
    return a;
}
static __device__ __forceinline__ float tanh_ap(float x) {
    float r; asm("tanh.approx.f32 %0, %1;" : "=f"(r) : "f"(x)); return r;
}
static __device__ __forceinline__ float sigmoid_f(float x) {
    return fmaf(0.5f, tanh_ap(0.5f * x), 0.5f);    // 1 MUFU
}

static __device__ __forceinline__ void ldsm4(uint32_t* r, uint32_t addr) {
    asm volatile("ldmatrix.sync.aligned.m8n8.x4.shared.b16 {%0,%1,%2,%3}, [%4];"
                 : "=r"(r[0]), "=r"(r[1]), "=r"(r[2]), "=r"(r[3]) : "r"(addr));
}
static __device__ __forceinline__ void mma16816(float* c, const uint32_t* a, uint32_t b0, uint32_t b1) {
    asm volatile("mma.sync.aligned.m16n8k16.row.col.f32.bf16.bf16.f32 "
                 "{%0,%1,%2,%3},{%4,%5,%6,%7},{%8,%9},{%0,%1,%2,%3};"
                 : "+f"(c[0]), "+f"(c[1]), "+f"(c[2]), "+f"(c[3])
                 : "r"(a[0]), "r"(a[1]), "r"(a[2]), "r"(a[3]), "r"(b0), "r"(b1));
}
static __device__ __forceinline__ uint32_t bfpack(float a, float b) {
    return ((uint32_t)__bfloat16_as_ushort(__float2bfloat16(b)) << 16)
         | (uint32_t)__bfloat16_as_ushort(__float2bfloat16(a));
}
static __device__ __forceinline__ float bfres(float w) {
    return w - __bfloat162float(__float2bfloat16(w));
}

// ---------- merged prep kernel ----------
__global__ void prep_kernel(const float* __restrict__ xs,
                            const float* __restrict__ W1,
                            const float* __restrict__ b1,
                            const float* __restrict__ Wg) {
    if (blockIdx.x < 64) {
        int idx = blockIdx.x * 256 + threadIdx.x;        // 16384
        int lane = idx & 31;
        int nt = (idx >> 5) & 31;
        int kt = (idx >> 10) & 7;
        int layer = idx >> 13;
        int n = nt * 8 + (lane >> 2);
        int k0 = kt * 16 + 2 * (lane & 3);
        const float* Wl = Wg + layer * 32768;
        float w00 = Wl[k0 * 256 + n];
        float w01 = Wl[(k0 + 1) * 256 + n];
        float w10 = Wl[(k0 + 8) * 256 + n];
        float w11 = Wl[(k0 + 9) * 256 + n];
        uint4 v;
        v.x = bfpack(w00, w01);
        v.y = bfpack(w10, w11);
        v.z = bfpack(bfres(w00), bfres(w01));
        v.w = bfpack(bfres(w10), bfres(w11));
        d_Wfrag[idx] = v;
    } else {
        int row = (blockIdx.x - 64) * 2 + (threadIdx.x >> 7);
        int c = threadIdx.x & 127;
        float s = b1[c];
        const float* xr = xs + row * 15;
#pragma unroll
        for (int f = 0; f < 15; f++) s = fmaf(xr[f], W1[(f + 1) * 128 + c], s);
        d_Base[row * 128 + c] = s;
    }
}

// ---------- main kernel ----------
__global__ void __launch_bounds__(128, 2)
gru_mma_kernel(const float* __restrict__ x,
               const float* __restrict__ W1,
               const float* __restrict__ W_out,
               const float* __restrict__ b_out,
               float* __restrict__ out) {
    extern __shared__ __align__(128) char sm[];
    const uint32_t sbase = smem_u32(sm);

    const int tid = threadIdx.x;
    const int w = tid >> 5;
    const int t = tid & 31;
    const int b = blockIdx.x >> 10;
    const int l = blockIdx.x & 1023;

    float* xr = (float*)(sm + XR_OFF);
    float* w1s = (float*)(sm + W1S_OFF);
    float* wouts = (float*)(sm + WOUT_OFF);

    if (tid < 64) xr[tid] = x[(b * 64 + tid) * 1024 + l];
    w1s[tid] = W1[tid];
    wouts[tid] = W_out[tid];
    __syncthreads();

    // ---- layer-0 feats -> swizzled bf16 A tile ----
    {
        const float4* base4 = (const float4*)d_Base;
        const float4* w14 = (const float4*)w1s;
#pragma unroll
        for (int it = 0; it < 16; it++) {
            int i = tid + 128 * it;
            int r = i >> 5, j = i & 31;
            float4 bs = base4[(b * 64 + r) * 32 + j];
            float4 wv = w14[j];
            float xv = xr[r];
            float v0 = fmaxf(fmaf(xv, wv.x, bs.x), 0.0f);
            float v1 = fmaxf(fmaf(xv, wv.y, bs.y), 0.0f);
            float v2 = fmaxf(fmaf(xv, wv.z, bs.z), 0.0f);
            float v3 = fmaxf(fmaf(xv, wv.w, bs.w), 0.0f);
            int off = r * 256 + ((((j >> 1) ^ (r & 7))) << 4) + 8 * (j & 1);
            *(uint2*)(sm + FEATS_HI + off) = make_uint2(bfpack(v0, v1), bfpack(v2, v3));
        }
    }
    __syncthreads();

#pragma unroll 1
    for (int layer = 0; layer < 2; layer++) {
        // ---- GEMM in two 32-col passes: pass p covers nt = w*8 + p*4 .. +3 ----
#pragma unroll 1
        for (int p = 0; p < 2; p++) {
            float acc[64];
#pragma unroll
            for (int i = 0; i < 64; i++) acc[i] = 0.0f;

            const uint4* wlp = d_Wfrag + layer * 8192 + (w * 8 + p * 4) * 32 + t;

            uint4 bw[2][4];
#pragma unroll
            for (int j = 0; j < 4; j++) bw[0][j] = wlp[j * 32];   // kt=0

#pragma unroll
            for (int kt = 0; kt < 8; kt++) {
                const int cur = kt & 1, nxt = cur ^ 1;

                uint32_t Ah[16];
#pragma unroll
                for (int mt = 0; mt < 4; mt++) {
                    int row = 16 * mt + (t & 7) + ((t >> 3) & 1) * 8;
                    uint32_t unit = (uint32_t)(2 * kt + (t >> 4));
                    uint32_t off = (uint32_t)(row * 256) + ((unit ^ (uint32_t)(row & 7)) << 4);
                    ldsm4(Ah + 4 * mt, sbase + FEATS_HI + off);
                }

                if (kt < 7) {
#pragma unroll
                    for (int j = 0; j < 4; j++) bw[nxt][j] = wlp[(kt + 1) * 1024 + j * 32];
                }

                // products outer: same-acc dependent mmas 16 issues apart
#pragma unroll
                for (int j = 0; j < 4; j++)
#pragma unroll
                    for (int mt = 0; mt < 4; mt++)
                        mma16816(acc + (j * 4 + mt) * 4, Ah + 4 * mt, bw[cur][j].x, bw[cur][j].y);
#pragma unroll
                for (int j = 0; j < 4; j++)
#pragma unroll
                    for (int mt = 0; mt < 4; mt++)
                        mma16816(acc + (j * 4 + mt) * 4, Ah + 4 * mt, bw[cur][j].z, bw[cur][j].w);
            }

            // store hg fragments: [n][256c] fp32, stride 260 words (conflict-free)
#pragma unroll
            for (int j = 0; j < 4; j++) {
                int col = (w * 8 + p * 4 + j) * 8 + 2 * (t & 3);
#pragma unroll
                for (int mt = 0; mt < 4; mt++) {
                    int r0 = 16 * mt + (t >> 2);
                    const float* c = acc + (j * 4 + mt) * 4;
                    *(float2*)(sm + HG_OFF + r0 * HG_STRIDE + col * 4) = make_float2(c[0], c[1]);
                    *(float2*)(sm + HG_OFF + (r0 + 8) * HG_STRIDE + col * 4) = make_float2(c[2], c[3]);
                }
            }
        }
        __syncthreads();

        // ---- minGRU scan over n, channel c = tid ----
        {
            const int c = tid;
            float h = 0.0f;
#pragma unroll
            for (int n = 0; n < 64; n++) {
                float hid = *(const float*)(sm + HG_OFF + n * HG_STRIDE + c * 4);
                float gat = *(const float*)(sm + HG_OFF + n * HG_STRIDE + (c + 128) * 4);
                float z = sigmoid_f(gat);
                float gg = (hid >= 0.0f) ? (hid + 0.5f) : sigmoid_f(hid);
                float v = z * gg;
                h = (n == 0) ? v : fmaf(1.0f - z, h, v);
                if (layer == 0) {
                    int off = n * 256 + ((((c >> 3) ^ (n & 7))) << 4) + ((2 * c) & 14);
                    *(__nv_bfloat16*)(sm + FEATS_HI + off) = __float2bfloat16(h);
                } else {
                    *(float*)(sm + HG_OFF + n * HG_STRIDE + c * 4) = h;
                }
            }
        }
        __syncthreads();
    }

    // ---- output ----
    if (tid < 64) {
        const int n = tid;
        const float4* row4 = (const float4*)(sm + HG_OFF + n * HG_STRIDE);
        const float4* wo4 = (const float4*)wouts;
        float s0 = 0.f, s1 = 0.f, s2 = 0.f, s3 = 0.f;
#pragma unroll
        for (int q = 0; q < 32; q++) {
            float4 hv = row4[q];
            float4 wv = wo4[q];
            s0 = fmaf(hv.x, wv.x, s0);
            s1 = fmaf(hv.y, wv.y, s1);
            s2 = fmaf(hv.z, wv.z, s2);
            s3 = fmaf(hv.w, wv.w, s3);
        }
        out[(b * 64 + n) * 1024 + l] = (s0 + s1) + (s2 + s3) + b_out[0] + xr[n];
    }
}

extern "C" void kernel_launch(void* const* d_in, const int* in_sizes, int n_in,
                              void* d_out, int out_size) {
    const float* xs = (const float*)d_in[0];
    const float* x  = (const float*)d_in[1];
    const float* W1 = (const float*)d_in[2];
    const float* b1 = (const float*)d_in[3];
    const float* Wg = (const float*)d_in[4];
    const float* Wo = (const float*)d_in[5];
    const float* bo = (const float*)d_in[6];
    float* out = (float*)d_out;

    cudaFuncSetAttribute(gru_mma_kernel, cudaFuncAttributeMaxDynamicSharedMemorySize, SMEM_TOTAL);
    prep_kernel<<<192, 256>>>(xs, W1, b1, Wg);
    gru_mma_kernel<<<4096, 128, SMEM_TOTAL>>>(x, W1, Wo, bo, out);
}

// round 8
// speedup vs baseline: 3.5471x; 1.2650x over previous
#include <cuda_runtime.h>
#include <cuda_bf16.h>
#include <cuda_fp16.h>
#include <cstdint>

// GRU_90821378441798 — HMMA 2-product bf16 split GEMM + in-register minGRU scan.
// R8: fp16 hg buffer (smem 84->50 KB) + 3 CTAs/SM.

#define FEATS_HI 0              // 64 rows x 256B swizzled bf16
#define HG_OFF   16384          // 64 rows x 528B (264 halfs, 256 used)
#define HG_STRIDE 528
#define XR_OFF   50176
#define W1S_OFF  50432
#define WOUT_OFF 50944
#define SMEM_TOTAL 51456

__device__ float d_Base[4 * 64 * 128];                    // xs@W1[1:,:]+b1
__device__ __align__(16) uint4 d_Wfrag[2 * 8 * 32 * 32];  // [layer][kt][nt][lane] = {bhi0,bhi1,blo0,blo1}

static __device__ __forceinline__ uint32_t smem_u32(const void* p) {
    uint32_t a;
    asm("{ .reg .u64 t; cvta.to.shared.u64 t, %1; cvt.u32.u64 %0, t; }" : "=r"(a) : "l"(p));
    return a;
}
static __device__ __forceinline__ float tanh_ap(float x) {
    float r; asm("tanh.approx.f32 %0, %1;" : "=f"(r) : "f"(x)); return r;
}
static __device__ __forceinline__ float sigmoid_f(float x) {
    return fmaf(0.5f, tanh_ap(0.5f * x), 0.5f);    // 1 MUFU
}

static __device__ __forceinline__ void ldsm4(uint32_t* r, uint32_t addr) {
    asm volatile("ldmatrix.sync.aligned.m8n8.x4.shared.b16 {%0,%1,%2,%3}, [%4];"
                 : "=r"(r[0]), "=r"(r[1]), "=r"(r[2]), "=r"(r[3]) : "r"(addr));
}
static __device__ __forceinline__ void mma16816(float* c, const uint32_t* a, uint32_t b0, uint32_t b1) {
    asm volatile("mma.sync.aligned.m16n8k16.row.col.f32.bf16.bf16.f32 "
                 "{%0,%1,%2,%3},{%4,%5,%6,%7},{%8,%9},{%0,%1,%2,%3};"
                 : "+f"(c[0]), "+f"(c[1]), "+f"(c[2]), "+f"(c[3])
                 : "r"(a[0]), "r"(a[1]), "r"(a[2]), "r"(a[3]), "r"(b0), "r"(b1));
}
static __device__ __forceinline__ uint32_t bfpack(float a, float b) {
    return ((uint32_t)__bfloat16_as_ushort(__float2bfloat16(b)) << 16)
         | (uint32_t)__bfloat16_as_ushort(__float2bfloat16(a));
}
static __device__ __forceinline__ float bfres(float w) {
    return w - __bfloat162float(__float2bfloat16(w));
}

// ---------- merged prep kernel ----------
__global__ void prep_kernel(const float* __restrict__ xs,
                            const float* __restrict__ W1,
                            const float* __restrict__ b1,
                            const float* __restrict__ Wg) {
    if (blockIdx.x < 64) {
        int idx = blockIdx.x * 256 + threadIdx.x;        // 16384
        int lane = idx & 31;
        int nt = (idx >> 5) & 31;
        int kt = (idx >> 10) & 7;
        int layer = idx >> 13;
        int n = nt * 8 + (lane >> 2);
        int k0 = kt * 16 + 2 * (lane & 3);
        const float* Wl = Wg + layer * 32768;
        float w00 = Wl[k0 * 256 + n];
        float w01 = Wl[(k0 + 1) * 256 + n];
        float w10 = Wl[(k0 + 8) * 256 + n];
        float w11 = Wl[(k0 + 9) * 256 + n];
        uint4 v;
        v.x = bfpack(w00, w01);
        v.y = bfpack(w10, w11);
        v.z = bfpack(bfres(w00), bfres(w01));
        v.w = bfpack(bfres(w10), bfres(w11));
        d_Wfrag[idx] = v;
    } else {
        int row = (blockIdx.x - 64) * 2 + (threadIdx.x >> 7);
        int c = threadIdx.x & 127;
        float s = b1[c];
        const float* xr = xs + row * 15;
#pragma unroll
        for (int f = 0; f < 15; f++) s = fmaf(xr[f], W1[(f + 1) * 128 + c], s);
        d_Base[row * 128 + c] = s;
    }
}

// ---------- main kernel ----------
__global__ void __launch_bounds__(128, 3)
gru_mma_kernel(const float* __restrict__ x,
               const float* __restrict__ W1,
               const float* __restrict__ W_out,
               const float* __restrict__ b_out,
               float* __restrict__ out) {
    extern __shared__ __align__(128) char sm[];
    const uint32_t sbase = smem_u32(sm);

    const int tid = threadIdx.x;
    const int w = tid >> 5;
    const int t = tid & 31;
    const int b = blockIdx.x >> 10;
    const int l = blockIdx.x & 1023;

    float* xr = (float*)(sm + XR_OFF);
    float* w1s = (float*)(sm + W1S_OFF);
    float* wouts = (float*)(sm + WOUT_OFF);

    if (tid < 64) xr[tid] = x[(b * 64 + tid) * 1024 + l];
    w1s[tid] = W1[tid];
    wouts[tid] = W_out[tid];
    __syncthreads();

    // ---- layer-0 feats -> swizzled bf16 A tile ----
    {
        const float4* base4 = (const float4*)d_Base;
        const float4* w14 = (const float4*)w1s;
#pragma unroll
        for (int it = 0; it < 16; it++) {
            int i = tid + 128 * it;
            int r = i >> 5, j = i & 31;
            float4 bs = base4[(b * 64 + r) * 32 + j];
            float4 wv = w14[j];
            float xv = xr[r];
            float v0 = fmaxf(fmaf(xv, wv.x, bs.x), 0.0f);
            float v1 = fmaxf(fmaf(xv, wv.y, bs.y), 0.0f);
            float v2 = fmaxf(fmaf(xv, wv.z, bs.z), 0.0f);
            float v3 = fmaxf(fmaf(xv, wv.w, bs.w), 0.0f);
            int off = r * 256 + ((((j >> 1) ^ (r & 7))) << 4) + 8 * (j & 1);
            *(uint2*)(sm + FEATS_HI + off) = make_uint2(bfpack(v0, v1), bfpack(v2, v3));
        }
    }
    __syncthreads();

#pragma unroll 1
    for (int layer = 0; layer < 2; layer++) {
        // ---- GEMM in two 32-col passes: pass p covers nt = w*8 + p*4 .. +3 ----
#pragma unroll 1
        for (int p = 0; p < 2; p++) {
            float acc[64];
#pragma unroll
            for (int i = 0; i < 64; i++) acc[i] = 0.0f;

            const uint4* wlp = d_Wfrag + layer * 8192 + (w * 8 + p * 4) * 32 + t;

            uint4 bw[2][4];
#pragma unroll
            for (int j = 0; j < 4; j++) bw[0][j] = wlp[j * 32];   // kt=0

#pragma unroll
            for (int kt = 0; kt < 8; kt++) {
                const int cur = kt & 1, nxt = cur ^ 1;

                uint32_t Ah[16];
#pragma unroll
                for (int mt = 0; mt < 4; mt++) {
                    int row = 16 * mt + (t & 7) + ((t >> 3) & 1) * 8;
                    uint32_t unit = (uint32_t)(2 * kt + (t >> 4));
                    uint32_t off = (uint32_t)(row * 256) + ((unit ^ (uint32_t)(row & 7)) << 4);
                    ldsm4(Ah + 4 * mt, sbase + FEATS_HI + off);
                }

                if (kt < 7) {
#pragma unroll
                    for (int j = 0; j < 4; j++) bw[nxt][j] = wlp[(kt + 1) * 1024 + j * 32];
                }

#pragma unroll
                for (int j = 0; j < 4; j++)
#pragma unroll
                    for (int mt = 0; mt < 4; mt++)
                        mma16816(acc + (j * 4 + mt) * 4, Ah + 4 * mt, bw[cur][j].x, bw[cur][j].y);
#pragma unroll
                for (int j = 0; j < 4; j++)
#pragma unroll
                    for (int mt = 0; mt < 4; mt++)
                        mma16816(acc + (j * 4 + mt) * 4, Ah + 4 * mt, bw[cur][j].z, bw[cur][j].w);
            }

            // store hg fragments as fp16: [n][264 halfs], conflict-free
#pragma unroll
            for (int j = 0; j < 4; j++) {
                int col = (w * 8 + p * 4 + j) * 8 + 2 * (t & 3);
#pragma unroll
                for (int mt = 0; mt < 4; mt++) {
                    int r0 = 16 * mt + (t >> 2);
                    const float* c = acc + (j * 4 + mt) * 4;
                    *(__half2*)(sm + HG_OFF + r0 * HG_STRIDE + col * 2) = __floats2half2_rn(c[0], c[1]);
                    *(__half2*)(sm + HG_OFF + (r0 + 8) * HG_STRIDE + col * 2) = __floats2half2_rn(c[2], c[3]);
                }
            }
        }
        __syncthreads();

        // ---- minGRU scan over n, channel c = tid ----
        {
            const int c = tid;
            float h = 0.0f;
#pragma unroll
            for (int n = 0; n < 64; n++) {
                float hid = __half2float(*(const __half*)(sm + HG_OFF + n * HG_STRIDE + c * 2));
                float gat = __half2float(*(const __half*)(sm + HG_OFF + n * HG_STRIDE + 256 + c * 2));
                float z = sigmoid_f(gat);
                float gg = (hid >= 0.0f) ? (hid + 0.5f) : sigmoid_f(hid);
                float v = z * gg;
                h = (n == 0) ? v : fmaf(1.0f - z, h, v);
                if (layer == 0) {
                    int off = n * 256 + ((((c >> 3) ^ (n & 7))) << 4) + ((2 * c) & 14);
                    *(__nv_bfloat16*)(sm + FEATS_HI + off) = __float2bfloat16(h);
                } else {
                    *(__half*)(sm + HG_OFF + n * HG_STRIDE + c * 2) = __float2half_rn(h);
                }
            }
        }
        __syncthreads();
    }

    // ---- output: out[b,n,l] = sum_c h[n][c]*Wout[c] + b_out + x ----
    if (tid < 64) {
        const int n = tid;
        const uint4* row4 = (const uint4*)(sm + HG_OFF + n * HG_STRIDE);   // 128 halfs = 16 uint4
        float s0 = 0.f, s1 = 0.f;
#pragma unroll
        for (int q = 0; q < 16; q++) {
            uint4 hv = row4[q];
            const float* wo = wouts + q * 8;
            float2 f0 = __half22float2(*(const __half2*)&hv.x);
            float2 f1 = __half22float2(*(const __half2*)&hv.y);
            float2 f2 = __half22float2(*(const __half2*)&hv.z);
            float2 f3 = __half22float2(*(const __half2*)&hv.w);
            s0 = fmaf(f0.x, wo[0], s0); s1 = fmaf(f0.y, wo[1], s1);
            s0 = fmaf(f1.x, wo[2], s0); s1 = fmaf(f1.y, wo[3], s1);
            s0 = fmaf(f2.x, wo[4], s0); s1 = fmaf(f2.y, wo[5], s1);
            s0 = fmaf(f3.x, wo[6], s0); s1 = fmaf(f3.y, wo[7], s1);
        }
        out[(b * 64 + n) * 1024 + l] = s0 + s1 + b_out[0] + xr[n];
    }
}

extern "C" void kernel_launch(void* const* d_in, const int* in_sizes, int n_in,
                              void* d_out, int out_size) {
    const float* xs = (const float*)d_in[0];
    const float* x  = (const float*)d_in[1];
    const float* W1 = (const float*)d_in[2];
    const float* b1 = (const float*)d_in[3];
    const float* Wg = (const float*)d_in[4];
    const float* Wo = (const float*)d_in[5];
    const float* bo = (const float*)d_in[6];
    float* out = (float*)d_out;

    cudaFuncSetAttribute(gru_mma_kernel, cudaFuncAttributeMaxDynamicSharedMemorySize, SMEM_TOTAL);
    prep_kernel<<<192, 256>>>(xs, W1, b1, Wg);
    gru_mma_kernel<<<4096, 128, SMEM_TOTAL>>>(x, W1, Wo, bo, out);
}

// round 9
// speedup vs baseline: 4.9346x; 1.3912x over previous
#include <cuda_runtime.h>
#include <cuda_bf16.h>
#include <cuda_fp16.h>
#include <cstdint>

// GRU_90821378441798 — HMMA plain-bf16 GEMM (single product) + in-register minGRU scan.
// R9: drop B_lo product (tensor work halved), uint2 weight fragments, 4 CTAs/SM.

#define FEATS_HI 0              // 64 rows x 256B swizzled bf16
#define HG_OFF   16384          // 64 rows x 528B (264 halfs, 256 used)
#define HG_STRIDE 528
#define XR_OFF   50176
#define W1S_OFF  50432
#define WOUT_OFF 50944
#define SMEM_TOTAL 51456

__device__ float d_Base[4 * 64 * 128];                    // xs@W1[1:,:]+b1
__device__ __align__(16) uint2 d_Wfrag[2 * 8 * 32 * 32];  // [layer][kt][nt][lane] = {bhi0,bhi1}

static __device__ __forceinline__ uint32_t smem_u32(const void* p) {
    uint32_t a;
    asm("{ .reg .u64 t; cvta.to.shared.u64 t, %1; cvt.u32.u64 %0, t; }" : "=r"(a) : "l"(p));
    return a;
}
static __device__ __forceinline__ float tanh_ap(float x) {
    float r; asm("tanh.approx.f32 %0, %1;" : "=f"(r) : "f"(x)); return r;
}
static __device__ __forceinline__ float sigmoid_f(float x) {
    return fmaf(0.5f, tanh_ap(0.5f * x), 0.5f);    // 1 MUFU
}

static __device__ __forceinline__ void ldsm4(uint32_t* r, uint32_t addr) {
    asm volatile("ldmatrix.sync.aligned.m8n8.x4.shared.b16 {%0,%1,%2,%3}, [%4];"
                 : "=r"(r[0]), "=r"(r[1]), "=r"(r[2]), "=r"(r[3]) : "r"(addr));
}
static __device__ __forceinline__ void mma16816(float* c, const uint32_t* a, uint32_t b0, uint32_t b1) {
    asm volatile("mma.sync.aligned.m16n8k16.row.col.f32.bf16.bf16.f32 "
                 "{%0,%1,%2,%3},{%4,%5,%6,%7},{%8,%9},{%0,%1,%2,%3};"
                 : "+f"(c[0]), "+f"(c[1]), "+f"(c[2]), "+f"(c[3])
                 : "r"(a[0]), "r"(a[1]), "r"(a[2]), "r"(a[3]), "r"(b0), "r"(b1));
}
static __device__ __forceinline__ uint32_t bfpack(float a, float b) {
    return ((uint32_t)__bfloat16_as_ushort(__float2bfloat16(b)) << 16)
         | (uint32_t)__bfloat16_as_ushort(__float2bfloat16(a));
}

// ---------- merged prep kernel ----------
__global__ void prep_kernel(const float* __restrict__ xs,
                            const float* __restrict__ W1,
                            const float* __restrict__ b1,
                            const float* __restrict__ Wg) {
    if (blockIdx.x < 64) {
        int idx = blockIdx.x * 256 + threadIdx.x;        // 16384
        int lane = idx & 31;
        int nt = (idx >> 5) & 31;
        int kt = (idx >> 10) & 7;
        int layer = idx >> 13;
        int n = nt * 8 + (lane >> 2);
        int k0 = kt * 16 + 2 * (lane & 3);
        const float* Wl = Wg + layer * 32768;
        float w00 = Wl[k0 * 256 + n];
        float w01 = Wl[(k0 + 1) * 256 + n];
        float w10 = Wl[(k0 + 8) * 256 + n];
        float w11 = Wl[(k0 + 9) * 256 + n];
        uint2 v;
        v.x = bfpack(w00, w01);
        v.y = bfpack(w10, w11);
        d_Wfrag[idx] = v;
    } else {
        int row = (blockIdx.x - 64) * 2 + (threadIdx.x >> 7);
        int c = threadIdx.x & 127;
        float s = b1[c];
        const float* xr = xs + row * 15;
#pragma unroll
        for (int f = 0; f < 15; f++) s = fmaf(xr[f], W1[(f + 1) * 128 + c], s);
        d_Base[row * 128 + c] = s;
    }
}

// ---------- main kernel ----------
__global__ void __launch_bounds__(128, 4)
gru_mma_kernel(const float* __restrict__ x,
               const float* __restrict__ W1,
               const float* __restrict__ W_out,
               const float* __restrict__ b_out,
               float* __restrict__ out) {
    extern __shared__ __align__(128) char sm[];
    const uint32_t sbase = smem_u32(sm);

    const int tid = threadIdx.x;
    const int w = tid >> 5;
    const int t = tid & 31;
    const int b = blockIdx.x >> 10;
    const int l = blockIdx.x & 1023;

    float* xr = (float*)(sm + XR_OFF);
    float* w1s = (float*)(sm + W1S_OFF);
    float* wouts = (float*)(sm + WOUT_OFF);

    if (tid < 64) xr[tid] = x[(b * 64 + tid) * 1024 + l];
    w1s[tid] = W1[tid];
    wouts[tid] = W_out[tid];
    __syncthreads();

    // ---- layer-0 feats -> swizzled bf16 A tile ----
    {
        const float4* base4 = (const float4*)d_Base;
        const float4* w14 = (const float4*)w1s;
#pragma unroll
        for (int it = 0; it < 16; it++) {
            int i = tid + 128 * it;
            int r = i >> 5, j = i & 31;
            float4 bs = base4[(b * 64 + r) * 32 + j];
            float4 wv = w14[j];
            float xv = xr[r];
            float v0 = fmaxf(fmaf(xv, wv.x, bs.x), 0.0f);
            float v1 = fmaxf(fmaf(xv, wv.y, bs.y), 0.0f);
            float v2 = fmaxf(fmaf(xv, wv.z, bs.z), 0.0f);
            float v3 = fmaxf(fmaf(xv, wv.w, bs.w), 0.0f);
            int off = r * 256 + ((((j >> 1) ^ (r & 7))) << 4) + 8 * (j & 1);
            *(uint2*)(sm + FEATS_HI + off) = make_uint2(bfpack(v0, v1), bfpack(v2, v3));
        }
    }
    __syncthreads();

#pragma unroll 1
    for (int layer = 0; layer < 2; layer++) {
        // ---- GEMM in two 32-col passes: pass p covers nt = w*8 + p*4 .. +3 ----
#pragma unroll 1
        for (int p = 0; p < 2; p++) {
            float acc[64];
#pragma unroll
            for (int i = 0; i < 64; i++) acc[i] = 0.0f;

            const uint2* wlp = d_Wfrag + layer * 8192 + (w * 8 + p * 4) * 32 + t;

            uint2 bw[2][4];
#pragma unroll
            for (int j = 0; j < 4; j++) bw[0][j] = wlp[j * 32];   // kt=0

#pragma unroll
            for (int kt = 0; kt < 8; kt++) {
                const int cur = kt & 1, nxt = cur ^ 1;

                uint32_t Ah[16];
#pragma unroll
                for (int mt = 0; mt < 4; mt++) {
                    int row = 16 * mt + (t & 7) + ((t >> 3) & 1) * 8;
                    uint32_t unit = (uint32_t)(2 * kt + (t >> 4));
                    uint32_t off = (uint32_t)(row * 256) + ((unit ^ (uint32_t)(row & 7)) << 4);
                    ldsm4(Ah + 4 * mt, sbase + FEATS_HI + off);
                }

                if (kt < 7) {
#pragma unroll
                    for (int j = 0; j < 4; j++) bw[nxt][j] = wlp[(kt + 1) * 1024 + j * 32];
                }

#pragma unroll
                for (int j = 0; j < 4; j++)
#pragma unroll
                    for (int mt = 0; mt < 4; mt++)
                        mma16816(acc + (j * 4 + mt) * 4, Ah + 4 * mt, bw[cur][j].x, bw[cur][j].y);
            }

            // store hg fragments as fp16: [n][264 halfs], conflict-free
#pragma unroll
            for (int j = 0; j < 4; j++) {
                int col = (w * 8 + p * 4 + j) * 8 + 2 * (t & 3);
#pragma unroll
                for (int mt = 0; mt < 4; mt++) {
                    int r0 = 16 * mt + (t >> 2);
                    const float* c = acc + (j * 4 + mt) * 4;
                    *(__half2*)(sm + HG_OFF + r0 * HG_STRIDE + col * 2) = __floats2half2_rn(c[0], c[1]);
                    *(__half2*)(sm + HG_OFF + (r0 + 8) * HG_STRIDE + col * 2) = __floats2half2_rn(c[2], c[3]);
                }
            }
        }
        __syncthreads();

        // ---- minGRU scan over n, channel c = tid ----
        {
            const int c = tid;
            float h = 0.0f;
#pragma unroll
            for (int n = 0; n < 64; n++) {
                float hid = __half2float(*(const __half*)(sm + HG_OFF + n * HG_STRIDE + c * 2));
                float gat = __half2float(*(const __half*)(sm + HG_OFF + n * HG_STRIDE + 256 + c * 2));
                float z = sigmoid_f(gat);
                float gg = (hid >= 0.0f) ? (hid + 0.5f) : sigmoid_f(hid);
                float v = z * gg;
                h = (n == 0) ? v : fmaf(1.0f - z, h, v);
                if (layer == 0) {
                    int off = n * 256 + ((((c >> 3) ^ (n & 7))) << 4) + ((2 * c) & 14);
                    *(__nv_bfloat16*)(sm + FEATS_HI + off) = __float2bfloat16(h);
                } else {
                    *(__half*)(sm + HG_OFF + n * HG_STRIDE + c * 2) = __float2half_rn(h);
                }
            }
        }
        __syncthreads();
    }

    // ---- output: out[b,n,l] = sum_c h[n][c]*Wout[c] + b_out + x ----
    if (tid < 64) {
        const int n = tid;
        const uint4* row4 = (const uint4*)(sm + HG_OFF + n * HG_STRIDE);   // 128 halfs = 16 uint4
        float s0 = 0.f, s1 = 0.f;
#pragma unroll
        for (int q = 0; q < 16; q++) {
            uint4 hv = row4[q];
            const float* wo = wouts + q * 8;
            float2 f0 = __half22float2(*(const __half2*)&hv.x);
            float2 f1 = __half22float2(*(const __half2*)&hv.y);
            float2 f2 = __half22float2(*(const __half2*)&hv.z);
            float2 f3 = __half22float2(*(const __half2*)&hv.w);
            s0 = fmaf(f0.x, wo[0], s0); s1 = fmaf(f0.y, wo[1], s1);
            s0 = fmaf(f1.x, wo[2], s0); s1 = fmaf(f1.y, wo[3], s1);
            s0 = fmaf(f2.x, wo[4], s0); s1 = fmaf(f2.y, wo[5], s1);
            s0 = fmaf(f3.x, wo[6], s0); s1 = fmaf(f3.y, wo[7], s1);
        }
        out[(b * 64 + n) * 1024 + l] = s0 + s1 + b_out[0] + xr[n];
    }
}

extern "C" void kernel_launch(void* const* d_in, const int* in_sizes, int n_in,
                              void* d_out, int out_size) {
    const float* xs = (const float*)d_in[0];
    const float* x  = (const float*)d_in[1];
    const float* W1 = (const float*)d_in[2];
    const float* b1 = (const float*)d_in[3];
    const float* Wg = (const float*)d_in[4];
    const float* Wo = (const float*)d_in[5];
    const float* bo = (const float*)d_in[6];
    float* out = (float*)d_out;

    cudaFuncSetAttribute(gru_mma_kernel, cudaFuncAttributeMaxDynamicSharedMemorySize, SMEM_TOTAL);
    prep_kernel<<<192, 256>>>(xs, W1, b1, Wg);
    gru_mma_kernel<<<4096, 128, SMEM_TOTAL>>>(x, W1, Wo, bo, out);
}

// round 11
// speedup vs baseline: 5.0698x; 1.0274x over previous
#include <cuda_runtime.h>
#include <cuda_bf16.h>
#include <cuda_fp16.h>
#include <cstdint>
#include <cstring>

// GRU_90821378441798 — HMMA bf16 GEMM + transposed-hg vectorized minGRU scan.
// R10b: same as R10, with the __half2_as_uint bit-cast helper fixed.

#define FEATS_HI 0              // 64 rows x 256B swizzled bf16
#define HGT_OFF  16384          // 128 rows (channel) x 272B: [64 hid | 64 gat | 8 pad] halfs
#define HGT_STRIDE 272
#define XR_OFF   51200
#define W1S_OFF  51456
#define WOUT_OFF 51968
#define SMEM_TOTAL 52480

__device__ float d_Base[4 * 64 * 128];                    // xs@W1[1:,:]+b1
__device__ __align__(16) uint2 d_Wfrag[2 * 8 * 32 * 32];  // [layer][kt][nt][lane] = {bhi0,bhi1}

static __device__ __forceinline__ uint32_t h2u(__half2 v) {
    uint32_t r; memcpy(&r, &v, 4); return r;
}
static __device__ __forceinline__ uint32_t smem_u32(const void* p) {
    uint32_t a;
    asm("{ .reg .u64 t; cvta.to.shared.u64 t, %1; cvt.u32.u64 %0, t; }" : "=r"(a) : "l"(p));
    return a;
}
static __device__ __forceinline__ float tanh_ap(float x) {
    float r; asm("tanh.approx.f32 %0, %1;" : "=f"(r) : "f"(x)); return r;
}
static __device__ __forceinline__ float sigmoid_f(float x) {
    return fmaf(0.5f, tanh_ap(0.5f * x), 0.5f);
}
static __device__ __forceinline__ uint32_t prmt(uint32_t a, uint32_t b, uint32_t sel) {
    uint32_t d; asm("prmt.b32 %0, %1, %2, %3;" : "=r"(d) : "r"(a), "r"(b), "r"(sel)); return d;
}

static __device__ __forceinline__ void ldsm4(uint32_t* r, uint32_t addr) {
    asm volatile("ldmatrix.sync.aligned.m8n8.x4.shared.b16 {%0,%1,%2,%3}, [%4];"
                 : "=r"(r[0]), "=r"(r[1]), "=r"(r[2]), "=r"(r[3]) : "r"(addr));
}
static __device__ __forceinline__ void mma16816(float* c, const uint32_t* a, uint32_t b0, uint32_t b1) {
    asm volatile("mma.sync.aligned.m16n8k16.row.col.f32.bf16.bf16.f32 "
                 "{%0,%1,%2,%3},{%4,%5,%6,%7},{%8,%9},{%0,%1,%2,%3};"
                 : "+f"(c[0]), "+f"(c[1]), "+f"(c[2]), "+f"(c[3])
                 : "r"(a[0]), "r"(a[1]), "r"(a[2]), "r"(a[3]), "r"(b0), "r"(b1));
}
static __device__ __forceinline__ uint32_t bfpack(float a, float b) {
    return ((uint32_t)__bfloat16_as_ushort(__float2bfloat16(b)) << 16)
         | (uint32_t)__bfloat16_as_ushort(__float2bfloat16(a));
}

// ---------- merged prep kernel ----------
__global__ void prep_kernel(const float* __restrict__ xs,
                            const float* __restrict__ W1,
                            const float* __restrict__ b1,
                            const float* __restrict__ Wg) {
    if (blockIdx.x < 64) {
        int idx = blockIdx.x * 256 + threadIdx.x;        // 16384
        int lane = idx & 31;
        int nt = (idx >> 5) & 31;
        int kt = (idx >> 10) & 7;
        int layer = idx >> 13;
        int n = nt * 8 + (lane >> 2);
        int k0 = kt * 16 + 2 * (lane & 3);
        const float* Wl = Wg + layer * 32768;
        uint2 v;
        v.x = bfpack(Wl[k0 * 256 + n], Wl[(k0 + 1) * 256 + n]);
        v.y = bfpack(Wl[(k0 + 8) * 256 + n], Wl[(k0 + 9) * 256 + n]);
        d_Wfrag[idx] = v;
    } else {
        int row = (blockIdx.x - 64) * 2 + (threadIdx.x >> 7);
        int c = threadIdx.x & 127;
        float s = b1[c];
        const float* xr = xs + row * 15;
#pragma unroll
        for (int f = 0; f < 15; f++) s = fmaf(xr[f], W1[(f + 1) * 128 + c], s);
        d_Base[row * 128 + c] = s;
    }
}

// ---------- main kernel ----------
__global__ void __launch_bounds__(128, 4)
gru_mma_kernel(const float* __restrict__ x,
               const float* __restrict__ W1,
               const float* __restrict__ W_out,
               const float* __restrict__ b_out,
               float* __restrict__ out) {
    extern __shared__ __align__(128) char sm[];
    const uint32_t sbase = smem_u32(sm);

    const int tid = threadIdx.x;
    const int w = tid >> 5;
    const int t = tid & 31;
    const int b = blockIdx.x >> 10;
    const int l = blockIdx.x & 1023;

    float* xr = (float*)(sm + XR_OFF);
    float* w1s = (float*)(sm + W1S_OFF);
    float* wouts = (float*)(sm + WOUT_OFF);

    if (tid < 64) xr[tid] = x[(b * 64 + tid) * 1024 + l];
    w1s[tid] = W1[tid];
    wouts[tid] = W_out[tid];
    __syncthreads();

    // ---- layer-0 feats -> swizzled bf16 A tile ----
    {
        const float4* base4 = (const float4*)d_Base;
        const float4* w14 = (const float4*)w1s;
#pragma unroll
        for (int it = 0; it < 16; it++) {
            int i = tid + 128 * it;
            int r = i >> 5, j = i & 31;
            float4 bs = base4[(b * 64 + r) * 32 + j];
            float4 wv = w14[j];
            float xv = xr[r];
            float v0 = fmaxf(fmaf(xv, wv.x, bs.x), 0.0f);
            float v1 = fmaxf(fmaf(xv, wv.y, bs.y), 0.0f);
            float v2 = fmaxf(fmaf(xv, wv.z, bs.z), 0.0f);
            float v3 = fmaxf(fmaf(xv, wv.w, bs.w), 0.0f);
            int off = r * 256 + ((((j >> 1) ^ (r & 7))) << 4) + 8 * (j & 1);
            *(uint2*)(sm + FEATS_HI + off) = make_uint2(bfpack(v0, v1), bfpack(v2, v3));
        }
    }
    __syncthreads();

    // store-pair prmt selector: bit2=0 -> (own.lo, partner.lo); bit2=1 -> (partner.hi, own.hi)
    const uint32_t psel = ((t >> 2) & 1) ? 0x3276u : 0x5410u;

#pragma unroll 1
    for (int layer = 0; layer < 2; layer++) {
        // ---- GEMM in two 32-col passes: pass p covers nt = w*8 + p*4 .. +3 ----
#pragma unroll 1
        for (int p = 0; p < 2; p++) {
            float acc[64];
#pragma unroll
            for (int i = 0; i < 64; i++) acc[i] = 0.0f;

            const uint2* wlp = d_Wfrag + layer * 8192 + (w * 8 + p * 4) * 32 + t;

            uint2 bw[2][4];
#pragma unroll
            for (int j = 0; j < 4; j++) bw[0][j] = wlp[j * 32];

#pragma unroll
            for (int kt = 0; kt < 8; kt++) {
                const int cur = kt & 1, nxt = cur ^ 1;

                uint32_t Ah[16];
#pragma unroll
                for (int mt = 0; mt < 4; mt++) {
                    int row = 16 * mt + (t & 7) + ((t >> 3) & 1) * 8;
                    uint32_t unit = (uint32_t)(2 * kt + (t >> 4));
                    uint32_t off = (uint32_t)(row * 256) + ((unit ^ (uint32_t)(row & 7)) << 4);
                    ldsm4(Ah + 4 * mt, sbase + FEATS_HI + off);
                }

                if (kt < 7) {
#pragma unroll
                    for (int j = 0; j < 4; j++) bw[nxt][j] = wlp[(kt + 1) * 1024 + j * 32];
                }

#pragma unroll
                for (int j = 0; j < 4; j++)
#pragma unroll
                    for (int mt = 0; mt < 4; mt++)
                        mma16816(acc + (j * 4 + mt) * 4, Ah + 4 * mt, bw[cur][j].x, bw[cur][j].y);
            }

            // ---- store hg fragments transposed: row = channel, halfs [n | n+1] ----
#pragma unroll
            for (int j = 0; j < 4; j++) {
                int cc = (w * 8 + p * 4 + j) * 8 + 2 * (t & 3) + ((t >> 2) & 1);
                char* rowp = sm + HGT_OFF + (cc & 127) * HGT_STRIDE + ((cc >> 7) << 7);
#pragma unroll
                for (int mt = 0; mt < 4; mt++) {
                    int np = 16 * mt + ((t >> 2) & 6);
                    const float* c = acc + (j * 4 + mt) * 4;
                    uint32_t h01 = h2u(__floats2half2_rn(c[0], c[1]));
                    uint32_t h23 = h2u(__floats2half2_rn(c[2], c[3]));
                    uint32_t v01 = __shfl_xor_sync(0xffffffffu, h01, 4);
                    uint32_t v23 = __shfl_xor_sync(0xffffffffu, h23, 4);
                    *(uint32_t*)(rowp + np * 2) = prmt(h01, v01, psel);        // rows np, np+1
                    *(uint32_t*)(rowp + np * 2 + 16) = prmt(h23, v23, psel);   // rows np+8, np+9
                }
            }
        }
        __syncthreads();

        // ---- minGRU scan over n, channel c = tid; vectorized row loads ----
        {
            const int c = tid;
            char* rowp = sm + HGT_OFF + c * HGT_STRIDE;
            float h = 0.0f;
#pragma unroll
            for (int ch = 0; ch < 8; ch++) {           // 8 n per chunk
                uint4 hv = *(const uint4*)(rowp + ch * 16);
                uint4 gv = *(const uint4*)(rowp + 128 + ch * 16);
                uint32_t hw[4] = {hv.x, hv.y, hv.z, hv.w};
                uint32_t gw[4] = {gv.x, gv.y, gv.z, gv.w};
                uint32_t packed[4];
#pragma unroll
                for (int wi = 0; wi < 4; wi++) {
                    float2 hf = __half22float2(*(const __half2*)&hw[wi]);
                    float2 gf = __half22float2(*(const __half2*)&gw[wi]);
                    int n0 = ch * 8 + 2 * wi;
                    float h0;
                    {
                        float z = sigmoid_f(gf.x);
                        float gg = (hf.x >= 0.0f) ? (hf.x + 0.5f) : sigmoid_f(hf.x);
                        float v = z * gg;
                        h = (n0 == 0) ? v : fmaf(1.0f - z, h, v);
                        h0 = h;
                    }
                    {
                        float z = sigmoid_f(gf.y);
                        float gg = (hf.y >= 0.0f) ? (hf.y + 0.5f) : sigmoid_f(hf.y);
                        float v = z * gg;
                        h = fmaf(1.0f - z, h, v);
                    }
                    if (layer == 0) {
                        int off0 = n0 * 256 + ((((c >> 3) ^ (n0 & 7))) << 4) + ((2 * c) & 14);
                        int n1 = n0 + 1;
                        int off1 = n1 * 256 + ((((c >> 3) ^ (n1 & 7))) << 4) + ((2 * c) & 14);
                        *(__nv_bfloat16*)(sm + FEATS_HI + off0) = __float2bfloat16(h0);
                        *(__nv_bfloat16*)(sm + FEATS_HI + off1) = __float2bfloat16(h);
                    } else {
                        packed[wi] = h2u(__floats2half2_rn(h0, h));
                    }
                }
                if (layer == 1) {     // vectorized in-place writeback (read already done)
                    *(uint4*)(rowp + ch * 16) = make_uint4(packed[0], packed[1], packed[2], packed[3]);
                }
            }
        }
        __syncthreads();
    }

    // ---- output: out[b,n,l] = sum_c h[c][n]*Wout[c] + b_out + x ----
    if (tid < 64) {
        const int n = tid;
        const char* hb = sm + HGT_OFF + n * 2;
        float s0 = 0.f, s1 = 0.f, s2 = 0.f, s3 = 0.f;
#pragma unroll
        for (int c = 0; c < 128; c += 4) {
            s0 = fmaf(__half2float(*(const __half*)(hb + (c + 0) * HGT_STRIDE)), wouts[c + 0], s0);
            s1 = fmaf(__half2float(*(const __half*)(hb + (c + 1) * HGT_STRIDE)), wouts[c + 1], s1);
            s2 = fmaf(__half2float(*(const __half*)(hb + (c + 2) * HGT_STRIDE)), wouts[c + 2], s2);
            s3 = fmaf(__half2float(*(const __half*)(hb + (c + 3) * HGT_STRIDE)), wouts[c + 3], s3);
        }
        out[(b * 64 + n) * 1024 + l] = (s0 + s1) + (s2 + s3) + b_out[0] + xr[n];
    }
}

extern "C" void kernel_launch(void* const* d_in, const int* in_sizes, int n_in,
                              void* d_out, int out_size) {
    const float* xs = (const float*)d_in[0];
    const float* x  = (const float*)d_in[1];
    const float* W1 = (const float*)d_in[2];
    const float* b1 = (const float*)d_in[3];
    const float* Wg = (const float*)d_in[4];
    const float* Wo = (const float*)d_in[5];
    const float* bo = (const float*)d_in[6];
    float* out = (float*)d_out;

    cudaFuncSetAttribute(gru_mma_kernel, cudaFuncAttributeMaxDynamicSharedMemorySize, SMEM_TOTAL);
    prep_kernel<<<192, 256>>>(xs, W1, b1, Wg);
    gru_mma_kernel<<<4096, 128, SMEM_TOTAL>>>(x, W1, Wo, bo, out);
}

// round 12
// speedup vs baseline: 5.3454x; 1.0544x over previous
#include <cuda_runtime.h>
#include <cuda_bf16.h>
#include <cuda_fp16.h>
#include <cstdint>
#include <cstring>

// GRU_90821378441798 — HMMA bf16 GEMM + warp-local minGRU scan.
// R12: warp owns its hid+gate columns (scan is warp-local; layer-1 barrier -> syncwarp),
//      uint4 weight fragments (2 kt per LDG).

#define FEATS_HI 0              // 64 rows x 256B swizzled bf16
#define HGT_OFF  16384          // 128 rows (channel) x 272B: [64 hid | 64 gat | pad]
#define HGT_STRIDE 272
#define XR_OFF   51200
#define W1S_OFF  51456
#define WOUT_OFF 51968
#define SMEM_TOTAL 52480

__device__ float d_Base[4 * 64 * 128];                     // xs@W1[1:,:]+b1
__device__ __align__(16) uint4 d_Wpack4[2 * 4 * 32 * 32];  // [layer][kp][nt][lane]: xy=kt2kp, zw=kt2kp+1

static __device__ __forceinline__ uint32_t h2u(__half2 v) {
    uint32_t r; memcpy(&r, &v, 4); return r;
}
static __device__ __forceinline__ uint32_t smem_u32(const void* p) {
    uint32_t a;
    asm("{ .reg .u64 t; cvta.to.shared.u64 t, %1; cvt.u32.u64 %0, t; }" : "=r"(a) : "l"(p));
    return a;
}
static __device__ __forceinline__ float tanh_ap(float x) {
    float r; asm("tanh.approx.f32 %0, %1;" : "=f"(r) : "f"(x)); return r;
}
static __device__ __forceinline__ float sigmoid_f(float x) {
    return fmaf(0.5f, tanh_ap(0.5f * x), 0.5f);
}
static __device__ __forceinline__ uint32_t prmt(uint32_t a, uint32_t b, uint32_t sel) {
    uint32_t d; asm("prmt.b32 %0, %1, %2, %3;" : "=r"(d) : "r"(a), "r"(b), "r"(sel)); return d;
}
static __device__ __forceinline__ void ldsm4(uint32_t* r, uint32_t addr) {
    asm volatile("ldmatrix.sync.aligned.m8n8.x4.shared.b16 {%0,%1,%2,%3}, [%4];"
                 : "=r"(r[0]), "=r"(r[1]), "=r"(r[2]), "=r"(r[3]) : "r"(addr));
}
static __device__ __forceinline__ void mma16816(float* c, const uint32_t* a, uint32_t b0, uint32_t b1) {
    asm volatile("mma.sync.aligned.m16n8k16.row.col.f32.bf16.bf16.f32 "
                 "{%0,%1,%2,%3},{%4,%5,%6,%7},{%8,%9},{%0,%1,%2,%3};"
                 : "+f"(c[0]), "+f"(c[1]), "+f"(c[2]), "+f"(c[3])
                 : "r"(a[0]), "r"(a[1]), "r"(a[2]), "r"(a[3]), "r"(b0), "r"(b1));
}
static __device__ __forceinline__ uint32_t bfpack(float a, float b) {
    return ((uint32_t)__bfloat16_as_ushort(__float2bfloat16(b)) << 16)
         | (uint32_t)__bfloat16_as_ushort(__float2bfloat16(a));
}

// ---------- merged prep kernel ----------
__global__ void prep_kernel(const float* __restrict__ xs,
                            const float* __restrict__ W1,
                            const float* __restrict__ b1,
                            const float* __restrict__ Wg) {
    if (blockIdx.x < 32) {
        int idx = blockIdx.x * 256 + threadIdx.x;        // 8192
        int lane = idx & 31;
        int nt = (idx >> 5) & 31;
        int kp = (idx >> 10) & 3;
        int layer = idx >> 12;
        int n = nt * 8 + (lane >> 2);
        const float* Wl = Wg + layer * 32768;
        uint4 v;
        {
            int k0 = (2 * kp) * 16 + 2 * (lane & 3);
            v.x = bfpack(Wl[k0 * 256 + n], Wl[(k0 + 1) * 256 + n]);
            v.y = bfpack(Wl[(k0 + 8) * 256 + n], Wl[(k0 + 9) * 256 + n]);
        }
        {
            int k0 = (2 * kp + 1) * 16 + 2 * (lane & 3);
            v.z = bfpack(Wl[k0 * 256 + n], Wl[(k0 + 1) * 256 + n]);
            v.w = bfpack(Wl[(k0 + 8) * 256 + n], Wl[(k0 + 9) * 256 + n]);
        }
        d_Wpack4[idx] = v;
    } else {
        int row = (blockIdx.x - 32) * 2 + (threadIdx.x >> 7);   // 0..255
        int c = threadIdx.x & 127;
        float s = b1[c];
        const float* xr = xs + row * 15;
#pragma unroll
        for (int f = 0; f < 15; f++) s = fmaf(xr[f], W1[(f + 1) * 128 + c], s);
        d_Base[row * 128 + c] = s;
    }
}

// ---------- main kernel ----------
__global__ void __launch_bounds__(128, 4)
gru_mma_kernel(const float* __restrict__ x,
               const float* __restrict__ W1,
               const float* __restrict__ W_out,
               const float* __restrict__ b_out,
               float* __restrict__ out) {
    extern __shared__ __align__(128) char sm[];
    const uint32_t sbase = smem_u32(sm);

    const int tid = threadIdx.x;
    const int w = tid >> 5;
    const int t = tid & 31;
    const int b = blockIdx.x >> 10;
    const int l = blockIdx.x & 1023;

    float* xr = (float*)(sm + XR_OFF);
    float* w1s = (float*)(sm + W1S_OFF);
    float* wouts = (float*)(sm + WOUT_OFF);

    if (tid < 64) xr[tid] = x[(b * 64 + tid) * 1024 + l];
    w1s[tid] = W1[tid];
    wouts[tid] = W_out[tid];
    __syncthreads();

    // ---- layer-0 feats -> swizzled bf16 A tile ----
    {
        const float4* base4 = (const float4*)d_Base;
        const float4* w14 = (const float4*)w1s;
#pragma unroll
        for (int it = 0; it < 16; it++) {
            int i = tid + 128 * it;
            int r = i >> 5, j = i & 31;
            float4 bs = base4[(b * 64 + r) * 32 + j];
            float4 wv = w14[j];
            float xv = xr[r];
            float v0 = fmaxf(fmaf(xv, wv.x, bs.x), 0.0f);
            float v1 = fmaxf(fmaf(xv, wv.y, bs.y), 0.0f);
            float v2 = fmaxf(fmaf(xv, wv.z, bs.z), 0.0f);
            float v3 = fmaxf(fmaf(xv, wv.w, bs.w), 0.0f);
            int off = r * 256 + ((((j >> 1) ^ (r & 7))) << 4) + 8 * (j & 1);
            *(uint2*)(sm + FEATS_HI + off) = make_uint2(bfpack(v0, v1), bfpack(v2, v3));
        }
    }
    __syncthreads();

    const uint32_t psel = ((t >> 2) & 1) ? 0x3276u : 0x5410u;
    const int c = w * 32 + t;               // this thread's scan channel
    char* crow = sm + HGT_OFF + c * HGT_STRIDE;

#pragma unroll 1
    for (int layer = 0; layer < 2; layer++) {
        // ---- GEMM: pass 0 = hid cols [32w,32w+32), pass 1 = gate cols [128+32w, +32) ----
#pragma unroll 1
        for (int p = 0; p < 2; p++) {
            float acc[64];
#pragma unroll
            for (int i = 0; i < 64; i++) acc[i] = 0.0f;

            const uint4* wlp = d_Wpack4 + layer * 4096 + (p * 16 + 4 * w) * 32 + t;

            uint4 bw[2][4];
#pragma unroll
            for (int j = 0; j < 4; j++) bw[0][j] = wlp[j * 32];

#pragma unroll
            for (int kp = 0; kp < 4; kp++) {
                const int cur = kp & 1, nxt = cur ^ 1;

                uint32_t Ah[16];
#pragma unroll
                for (int mt = 0; mt < 4; mt++) {        // kt = 2*kp
                    int row = 16 * mt + (t & 7) + ((t >> 3) & 1) * 8;
                    uint32_t unit = (uint32_t)(4 * kp + (t >> 4));
                    uint32_t off = (uint32_t)(row * 256) + ((unit ^ (uint32_t)(row & 7)) << 4);
                    ldsm4(Ah + 4 * mt, sbase + FEATS_HI + off);
                }
                if (kp < 3) {
#pragma unroll
                    for (int j = 0; j < 4; j++) bw[nxt][j] = wlp[(kp + 1) * 1024 + j * 32];
                }
#pragma unroll
                for (int j = 0; j < 4; j++)
#pragma unroll
                    for (int mt = 0; mt < 4; mt++)
                        mma16816(acc + (j * 4 + mt) * 4, Ah + 4 * mt, bw[cur][j].x, bw[cur][j].y);

#pragma unroll
                for (int mt = 0; mt < 4; mt++) {        // kt = 2*kp+1
                    int row = 16 * mt + (t & 7) + ((t >> 3) & 1) * 8;
                    uint32_t unit = (uint32_t)(4 * kp + 2 + (t >> 4));
                    uint32_t off = (uint32_t)(row * 256) + ((unit ^ (uint32_t)(row & 7)) << 4);
                    ldsm4(Ah + 4 * mt, sbase + FEATS_HI + off);
                }
#pragma unroll
                for (int j = 0; j < 4; j++)
#pragma unroll
                    for (int mt = 0; mt < 4; mt++)
                        mma16816(acc + (j * 4 + mt) * 4, Ah + 4 * mt, bw[cur][j].z, bw[cur][j].w);
            }

            // ---- store hg fragments transposed: row = channel ----
#pragma unroll
            for (int j = 0; j < 4; j++) {
                int cc = (p * 16 + 4 * w + j) * 8 + 2 * (t & 3) + ((t >> 2) & 1);
                char* rowp = sm + HGT_OFF + (cc & 127) * HGT_STRIDE + ((cc >> 7) << 7);
#pragma unroll
                for (int mt = 0; mt < 4; mt++) {
                    int np = 16 * mt + ((t >> 2) & 6);
                    const float* cp = acc + (j * 4 + mt) * 4;
                    uint32_t h01 = h2u(__floats2half2_rn(cp[0], cp[1]));
                    uint32_t h23 = h2u(__floats2half2_rn(cp[2], cp[3]));
                    uint32_t v01 = __shfl_xor_sync(0xffffffffu, h01, 4);
                    uint32_t v23 = __shfl_xor_sync(0xffffffffu, h23, 4);
                    *(uint32_t*)(rowp + np * 2) = prmt(h01, v01, psel);
                    *(uint32_t*)(rowp + np * 2 + 16) = prmt(h23, v23, psel);
                }
            }
        }

        // layer 0: CTA barrier (FEATS is about to be overwritten; all ldsm must be done).
        // layer 1: warp-local only — scan consumes own warp's HGT rows.
        if (layer == 0) __syncthreads();
        else            __syncwarp();

        // ---- minGRU scan over n for channel c (warp-local data) ----
        {
            float h = 0.0f;
#pragma unroll
            for (int ch = 0; ch < 8; ch++) {
                uint4 hv = *(const uint4*)(crow + ch * 16);
                uint4 gv = *(const uint4*)(crow + 128 + ch * 16);
                uint32_t hw[4] = {hv.x, hv.y, hv.z, hv.w};
                uint32_t gw[4] = {gv.x, gv.y, gv.z, gv.w};
                uint32_t packed[4];
#pragma unroll
                for (int wi = 0; wi < 4; wi++) {
                    float2 hf = __half22float2(*(const __half2*)&hw[wi]);
                    float2 gf = __half22float2(*(const __half2*)&gw[wi]);
                    int n0 = ch * 8 + 2 * wi;
                    float h0;
                    {
                        float z = sigmoid_f(gf.x);
                        float gg = (hf.x >= 0.0f) ? (hf.x + 0.5f) : sigmoid_f(hf.x);
                        float v = z * gg;
                        h = (n0 == 0) ? v : fmaf(1.0f - z, h, v);
                        h0 = h;
                    }
                    {
                        float z = sigmoid_f(gf.y);
                        float gg = (hf.y >= 0.0f) ? (hf.y + 0.5f) : sigmoid_f(hf.y);
                        float v = z * gg;
                        h = fmaf(1.0f - z, h, v);
                    }
                    if (layer == 0) {
                        int off0 = n0 * 256 + ((((c >> 3) ^ (n0 & 7))) << 4) + ((2 * c) & 14);
                        int n1 = n0 + 1;
                        int off1 = n1 * 256 + ((((c >> 3) ^ (n1 & 7))) << 4) + ((2 * c) & 14);
                        *(__nv_bfloat16*)(sm + FEATS_HI + off0) = __float2bfloat16(h0);
                        *(__nv_bfloat16*)(sm + FEATS_HI + off1) = __float2bfloat16(h);
                    } else {
                        packed[wi] = h2u(__floats2half2_rn(h0, h));
                    }
                }
                if (layer == 1) {
                    *(uint4*)(crow + ch * 16) = make_uint4(packed[0], packed[1], packed[2], packed[3]);
                }
            }
        }
        __syncthreads();    // layer0: FEATS complete for next GEMM; layer1: HGT complete for epilogue
    }

    // ---- output: out[b,n,l] = sum_c h[c][n]*Wout[c] + b_out + x ----
    if (tid < 64) {
        const int n = tid;
        const char* hb = sm + HGT_OFF + n * 2;
        float s0 = 0.f, s1 = 0.f, s2 = 0.f, s3 = 0.f;
#pragma unroll
        for (int q = 0; q < 128; q += 4) {
            s0 = fmaf(__half2float(*(const __half*)(hb + (q + 0) * HGT_STRIDE)), wouts[q + 0], s0);
            s1 = fmaf(__half2float(*(const __half*)(hb + (q + 1) * HGT_STRIDE)), wouts[q + 1], s1);
            s2 = fmaf(__half2float(*(const __half*)(hb + (q + 2) * HGT_STRIDE)), wouts[q + 2], s2);
            s3 = fmaf(__half2float(*(const __half*)(hb + (q + 3) * HGT_STRIDE)), wouts[q + 3], s3);
        }
        out[(b * 64 + n) * 1024 + l] = (s0 + s1) + (s2 + s3) + b_out[0] + xr[n];
    }
}

extern "C" void kernel_launch(void* const* d_in, const int* in_sizes, int n_in,
                              void* d_out, int out_size) {
    const float* xs = (const float*)d_in[0];
    const float* x  = (const float*)d_in[1];
    const float* W1 = (const float*)d_in[2];
    const float* b1 = (const float*)d_in[3];
    const float* Wg = (const float*)d_in[4];
    const float* Wo = (const float*)d_in[5];
    const float* bo = (const float*)d_in[6];
    float* out = (float*)d_out;

    cudaFuncSetAttribute(gru_mma_kernel, cudaFuncAttributeMaxDynamicSharedMemorySize, SMEM_TOTAL);
    prep_kernel<<<160, 256>>>(xs, W1, b1, Wg);
    gru_mma_kernel<<<4096, 128, SMEM_TOTAL>>>(x, W1, Wo, bo, out);
}